// round 1
// baseline (speedup 1.0000x reference)
#include <cuda_runtime.h>
#include <math.h>

#define B_  2
#define S_  2048
#define D_  1024
#define H_  16
#define DK_ 64
#define M_  (B_*S_)

// Scratch (allocation-free contract: __device__ globals)
__device__ float g_Q[B_*H_*S_*DK_];
__device__ float g_K[B_*H_*S_*DK_];
__device__ float g_V[B_*H_*S_*DK_];
__device__ float g_AO[(size_t)M_*D_];

// ---------------------------------------------------------------------------
// Tiled SGEMM: C[m,n] = sum_k A[m,k] * W[n,k]   (A: [M,K] row-major, W: [N,K])
// DEST: 0 = write Cout row-major [M,N] (final output projection)
//       1 = g_Q with RoPE + [B,H,S,DK] remap
//       2 = g_K with RoPE + [B,H,S,DK] remap
//       3 = g_V with [B,H,S,DK] remap
// ---------------------------------------------------------------------------
template<int DEST>
__global__ __launch_bounds__(256)
void gemm_bt(const float* __restrict__ A, const float* __restrict__ W,
             float* __restrict__ Cout, const int* __restrict__ tokpos)
{
    constexpr int BM = 128, BN = 64, BK = 16;
    __shared__ __align__(16) float As[BK][132];  // [k][m], padded
    __shared__ __align__(16) float Bs[BK][68];   // [k][n], padded

    const int tid = threadIdx.x;
    const int tx  = tid & 15;     // n-dim thread coord (4 cols each)
    const int ty  = tid >> 4;     // m-dim thread coord (8 rows each)
    const int m0  = blockIdx.y * BM;
    const int n0  = blockIdx.x * BN;

    float acc[8][4];
#pragma unroll
    for (int i = 0; i < 8; i++)
#pragma unroll
        for (int j = 0; j < 4; j++) acc[i][j] = 0.f;

    const float* Ab = A + (size_t)m0 * D_;
    const float* Wb = W + (size_t)n0 * D_;

    for (int kk = 0; kk < D_; kk += BK) {
        // A tile: 128x16 floats = 512 float4, 2 per thread
#pragma unroll
        for (int i = 0; i < 2; i++) {
            int idx = tid + i * 256;
            int r = idx >> 2, c = (idx & 3) << 2;
            float4 v = *(const float4*)(Ab + (size_t)r * D_ + kk + c);
            As[c+0][r] = v.x; As[c+1][r] = v.y; As[c+2][r] = v.z; As[c+3][r] = v.w;
        }
        // W tile: 64x16 floats = 256 float4, 1 per thread
        {
            int r = tid >> 2, c = (tid & 3) << 2;
            float4 v = *(const float4*)(Wb + (size_t)r * D_ + kk + c);
            Bs[c+0][r] = v.x; Bs[c+1][r] = v.y; Bs[c+2][r] = v.z; Bs[c+3][r] = v.w;
        }
        __syncthreads();

#pragma unroll
        for (int k = 0; k < BK; k++) {
            float a[8], bv[4];
            *(float4*)(a)     = *(const float4*)(&As[k][ty*8]);
            *(float4*)(a + 4) = *(const float4*)(&As[k][ty*8 + 4]);
            *(float4*)(bv)    = *(const float4*)(&Bs[k][tx*4]);
#pragma unroll
            for (int i = 0; i < 8; i++)
#pragma unroll
                for (int j = 0; j < 4; j++)
                    acc[i][j] = fmaf(a[i], bv[j], acc[i][j]);
        }
        __syncthreads();
    }

    const int ncol = n0 + tx * 4;

    if (DEST == 0) {
#pragma unroll
        for (int i = 0; i < 8; i++) {
            int m = m0 + ty * 8 + i;
            float4 r = make_float4(acc[i][0], acc[i][1], acc[i][2], acc[i][3]);
            *(float4*)(Cout + (size_t)m * D_ + ncol) = r;
        }
    } else {
        float* Dst = (DEST == 1) ? g_Q : (DEST == 2) ? g_K : g_V;
        const int h  = ncol >> 6;
        const int dk = ncol & 63;            // multiple of 4 -> 2 RoPE pairs local
        float f0 = 0.f, f1 = 0.f;
        if (DEST != 3) {
            // freqs = 10000^(-2p/64); pair p0 covers cols (dk,dk+1), p1 (dk+2,dk+3)
            f0 = powf(10000.f, -(float)dk       / 64.f);
            f1 = powf(10000.f, -(float)(dk + 2) / 64.f);
        }
#pragma unroll
        for (int i = 0; i < 8; i++) {
            int m = m0 + ty * 8 + i;
            int b = m >> 11;                 // / S_
            int s = m & (S_ - 1);
            float4 r;
            if (DEST == 3) {
                r = make_float4(acc[i][0], acc[i][1], acc[i][2], acc[i][3]);
            } else {
                float pos = (float)tokpos[s];
                float sn0, cs0, sn1, cs1;
                sincosf(pos * f0, &sn0, &cs0);
                sincosf(pos * f1, &sn1, &cs1);
                r.x = acc[i][0] * cs0 - acc[i][1] * sn0;
                r.y = acc[i][0] * sn0 + acc[i][1] * cs0;
                r.z = acc[i][2] * cs1 - acc[i][3] * sn1;
                r.w = acc[i][2] * sn1 + acc[i][3] * cs1;
            }
            size_t off = ((size_t)((b * H_ + h) * S_ + s)) * DK_ + dk;
            *(float4*)(Dst + off) = r;
        }
    }
}

// ---------------------------------------------------------------------------
// Flash attention (fp32, causal). One CTA = one (b, h, 64-query tile).
// Layouts: g_Q/g_K/g_V are [B,H,S,DK]; output g_AO is [B,S,H*DK].
// ---------------------------------------------------------------------------
__global__ __launch_bounds__(256)
void attn_kernel()
{
    extern __shared__ __align__(16) float sm[];
    float (*Qs)[68] = (float(*)[68])(sm);               // [d][q]  transposed
    float (*Ks)[68] = (float(*)[68])(sm + 1 * 64 * 68); // [d][k]  transposed
    float (*Vs)[68] = (float(*)[68])(sm + 2 * 64 * 68); // [j][d]  natural
    float (*Ps)[68] = (float(*)[68])(sm + 3 * 64 * 68); // [i][j]

    const int tid = threadIdx.x;
    const int tx  = tid & 15;   // key / headdim coord (4 each)
    const int ty  = tid >> 4;   // query coord (4 each)
    const int qt  = (int)(gridDim.x - 1 - blockIdx.x);  // big tiles launch first
    const int h   = blockIdx.y, b = blockIdx.z;
    const size_t base = ((size_t)(b * H_ + h)) * S_ * DK_;
    const int q0 = qt * 64;

    // Load Q tile transposed into smem (64 q x 64 d)
#pragma unroll
    for (int i = 0; i < 4; i++) {
        int idx = tid + i * 256;
        int r = idx >> 4, c = (idx & 15) << 2;
        float4 v = *(const float4*)(g_Q + base + (size_t)(q0 + r) * DK_ + c);
        Qs[c+0][r] = v.x; Qs[c+1][r] = v.y; Qs[c+2][r] = v.z; Qs[c+3][r] = v.w;
    }

    float mi[4], li[4], o[4][4];
#pragma unroll
    for (int i = 0; i < 4; i++) {
        mi[i] = -1e30f; li[i] = 0.f;
#pragma unroll
        for (int j = 0; j < 4; j++) o[i][j] = 0.f;
    }

    for (int kt = 0; kt <= qt; kt++) {
        const int k0 = kt * 64;
        __syncthreads();   // previous iter's PV reads done (also covers Q load)
#pragma unroll
        for (int i = 0; i < 4; i++) {
            int idx = tid + i * 256;
            int r = idx >> 4, c = (idx & 15) << 2;
            float4 v = *(const float4*)(g_K + base + (size_t)(k0 + r) * DK_ + c);
            Ks[c+0][r] = v.x; Ks[c+1][r] = v.y; Ks[c+2][r] = v.z; Ks[c+3][r] = v.w;
            float4 w = *(const float4*)(g_V + base + (size_t)(k0 + r) * DK_ + c);
            *(float4*)(&Vs[r][c]) = w;
        }
        __syncthreads();

        // S = Q K^T / 8 (4x4 block per thread)
        float s[4][4];
#pragma unroll
        for (int i = 0; i < 4; i++)
#pragma unroll
            for (int j = 0; j < 4; j++) s[i][j] = 0.f;
#pragma unroll
        for (int d = 0; d < 64; d++) {
            float4 qv = *(const float4*)(&Qs[d][ty*4]);
            float4 kv = *(const float4*)(&Ks[d][tx*4]);
            float qa[4] = {qv.x, qv.y, qv.z, qv.w};
            float ka[4] = {kv.x, kv.y, kv.z, kv.w};
#pragma unroll
            for (int i = 0; i < 4; i++)
#pragma unroll
                for (int j = 0; j < 4; j++)
                    s[i][j] = fmaf(qa[i], ka[j], s[i][j]);
        }
#pragma unroll
        for (int i = 0; i < 4; i++)
#pragma unroll
            for (int j = 0; j < 4; j++) s[i][j] *= 0.125f;

        if (kt == qt) {   // causal mask on diagonal tile
#pragma unroll
            for (int i = 0; i < 4; i++)
#pragma unroll
                for (int j = 0; j < 4; j++)
                    if (k0 + tx*4 + j > q0 + ty*4 + i) s[i][j] = -1e30f;
        }

        // Online softmax: row stats across the 16-lane group owning each row
#pragma unroll
        for (int i = 0; i < 4; i++) {
            float v = fmaxf(fmaxf(s[i][0], s[i][1]), fmaxf(s[i][2], s[i][3]));
            v = fmaxf(v, __shfl_xor_sync(0xffffffffu, v, 8));
            v = fmaxf(v, __shfl_xor_sync(0xffffffffu, v, 4));
            v = fmaxf(v, __shfl_xor_sync(0xffffffffu, v, 2));
            v = fmaxf(v, __shfl_xor_sync(0xffffffffu, v, 1));
            float mnew = fmaxf(mi[i], v);
            float corr = __expf(mi[i] - mnew);
            float rs = 0.f;
#pragma unroll
            for (int j = 0; j < 4; j++) { s[i][j] = __expf(s[i][j] - mnew); rs += s[i][j]; }
            rs += __shfl_xor_sync(0xffffffffu, rs, 8);
            rs += __shfl_xor_sync(0xffffffffu, rs, 4);
            rs += __shfl_xor_sync(0xffffffffu, rs, 2);
            rs += __shfl_xor_sync(0xffffffffu, rs, 1);
            li[i] = li[i] * corr + rs;
            mi[i] = mnew;
#pragma unroll
            for (int j = 0; j < 4; j++) o[i][j] *= corr;
        }

        // Stage P through smem, then O += P V
#pragma unroll
        for (int i = 0; i < 4; i++)
            *(float4*)(&Ps[ty*4 + i][tx*4]) =
                make_float4(s[i][0], s[i][1], s[i][2], s[i][3]);
        __syncthreads();

#pragma unroll 4
        for (int j = 0; j < 64; j++) {
            float4 vv = *(const float4*)(&Vs[j][tx*4]);
#pragma unroll
            for (int i = 0; i < 4; i++) {
                float p = Ps[ty*4 + i][j];
                o[i][0] = fmaf(p, vv.x, o[i][0]);
                o[i][1] = fmaf(p, vv.y, o[i][1]);
                o[i][2] = fmaf(p, vv.z, o[i][2]);
                o[i][3] = fmaf(p, vv.w, o[i][3]);
            }
        }
    }

    // Epilogue: normalize, write [B,S,H*DK]
#pragma unroll
    for (int i = 0; i < 4; i++) {
        int row = q0 + ty*4 + i;
        float inv = 1.f / li[i];
        float4 r = make_float4(o[i][0]*inv, o[i][1]*inv, o[i][2]*inv, o[i][3]*inv);
        *(float4*)(g_AO + ((size_t)b * S_ + row) * D_ + h * DK_ + tx*4) = r;
    }
}

// ---------------------------------------------------------------------------
extern "C" void kernel_launch(void* const* d_in, const int* in_sizes, int n_in,
                              void* d_out, int out_size)
{
    const float* x   = (const float*)d_in[0];   // [B,S,D]
    const float* qw  = (const float*)d_in[1];   // [D,D]
    const float* kw  = (const float*)d_in[2];
    const float* vw  = (const float*)d_in[3];
    const float* ow  = (const float*)d_in[4];
    // d_in[5] = mask (tril, known) — unused
    const int*   tp  = (const int*)d_in[6];     // [S]
    float* out = (float*)d_out;

    dim3 ggrid(D_ / 64, M_ / 128);   // (16, 32)

    gemm_bt<1><<<ggrid, 256>>>(x, qw, nullptr, tp);   // Q + RoPE
    gemm_bt<2><<<ggrid, 256>>>(x, kw, nullptr, tp);   // K + RoPE
    gemm_bt<3><<<ggrid, 256>>>(x, vw, nullptr, tp);   // V

    const int attn_smem = 4 * 64 * 68 * (int)sizeof(float);  // 69632 B
    cudaFuncSetAttribute(attn_kernel,
                         cudaFuncAttributeMaxDynamicSharedMemorySize, attn_smem);
    dim3 agrid(S_ / 64, H_, B_);     // (32, 16, 2)
    attn_kernel<<<agrid, 256, attn_smem>>>();

    float* aop = nullptr;
    cudaGetSymbolAddress((void**)&aop, g_AO);
    gemm_bt<0><<<ggrid, 256>>>(aop, ow, out, tp);     // output projection
}

// round 3
// speedup vs baseline: 1.5141x; 1.5141x over previous
#include <cuda_runtime.h>
#include <cuda_bf16.h>
#include <math.h>
#include <stdint.h>

#define B_  2
#define S_  2048
#define D_  1024
#define H_  16
#define DK_ 64
#define M_  (B_*S_)

// ---------------------------------------------------------------------------
// Scratch (__device__ globals; allocation-free contract)
// ---------------------------------------------------------------------------
__device__ __align__(16) __nv_bfloat16 g_Xhi[M_*D_];
__device__ __align__(16) __nv_bfloat16 g_Xlo[M_*D_];
__device__ __align__(16) __nv_bfloat16 g_Whi[4*(size_t)D_*D_];   // [mat][n][k]
__device__ __align__(16) __nv_bfloat16 g_Wlo[4*(size_t)D_*D_];
__device__ __align__(16) __nv_bfloat16 g_AOhi[M_*D_];
__device__ __align__(16) __nv_bfloat16 g_AOlo[M_*D_];
__device__ float g_Q[B_*H_*S_*DK_];
__device__ float g_K[B_*H_*S_*DK_];
__device__ float g_V[B_*H_*S_*DK_];

// ---------------------------------------------------------------------------
// Small PTX wrappers (all arch-neutral: sm_80-class instructions)
// ---------------------------------------------------------------------------
__device__ __forceinline__ uint32_t smem_u32(const void* p) {
    uint32_t a;
    asm("{ .reg .u64 t; cvta.to.shared.u64 t, %1; cvt.u32.u64 %0, t; }"
        : "=r"(a) : "l"(p));
    return a;
}
__device__ __forceinline__ void cp16(uint32_t dst, const void* src) {
    asm volatile("cp.async.cg.shared.global [%0], [%1], 16;"
                 :: "r"(dst), "l"(src));
}
#define CP_COMMIT() asm volatile("cp.async.commit_group;")
#define CP_WAIT1()  asm volatile("cp.async.wait_group 1;")

__device__ __forceinline__ void ldmA(uint32_t (&a)[4], uint32_t addr) {
    asm volatile("ldmatrix.sync.aligned.m8n8.x4.shared.b16 {%0,%1,%2,%3}, [%4];"
                 : "=r"(a[0]), "=r"(a[1]), "=r"(a[2]), "=r"(a[3]) : "r"(addr));
}
__device__ __forceinline__ void ldmB(uint32_t (&b)[2], uint32_t addr) {
    asm volatile("ldmatrix.sync.aligned.m8n8.x2.shared.b16 {%0,%1}, [%2];"
                 : "=r"(b[0]), "=r"(b[1]) : "r"(addr));
}
__device__ __forceinline__ void mma_bf16(float (&d)[4], const uint32_t (&a)[4],
                                         const uint32_t (&b)[2]) {
    asm volatile(
        "mma.sync.aligned.m16n8k16.row.col.f32.bf16.bf16.f32 "
        "{%0,%1,%2,%3}, {%4,%5,%6,%7}, {%8,%9}, {%0,%1,%2,%3};"
        : "+f"(d[0]), "+f"(d[1]), "+f"(d[2]), "+f"(d[3])
        : "r"(a[0]), "r"(a[1]), "r"(a[2]), "r"(a[3]), "r"(b[0]), "r"(b[1]));
}

// ---------------------------------------------------------------------------
// fp32 -> bf16 (hi, lo) split
// ---------------------------------------------------------------------------
__global__ __launch_bounds__(256)
void split_bf16(const float* __restrict__ src, __nv_bfloat16* __restrict__ hi,
                __nv_bfloat16* __restrict__ lo, int n)
{
    int i = (blockIdx.x * blockDim.x + threadIdx.x) * 4;
    if (i >= n) return;
    float4 v = *(const float4*)(src + i);
    float f[4] = {v.x, v.y, v.z, v.w};
    __nv_bfloat16 h[4], l[4];
#pragma unroll
    for (int j = 0; j < 4; j++) {
        h[j] = __float2bfloat16(f[j]);
        l[j] = __float2bfloat16(f[j] - __bfloat162float(h[j]));
    }
    *(__nv_bfloat162*)(hi + i)     = __halves2bfloat162(h[0], h[1]);
    *(__nv_bfloat162*)(hi + i + 2) = __halves2bfloat162(h[2], h[3]);
    *(__nv_bfloat162*)(lo + i)     = __halves2bfloat162(l[0], l[1]);
    *(__nv_bfloat162*)(lo + i + 2) = __halves2bfloat162(l[2], l[3]);
}

// ---------------------------------------------------------------------------
// Split-bf16 tensor-core GEMM via mma.sync (HMMA):
//   C[m,n] = sum_k A[m,k]*W[n,k],  A = Ahi+Alo, W = Whi+Wlo (bf16 each),
//   C ≈ Ahi*Whi + Ahi*Wlo + Alo*Whi  (fp32 accumulate)
// CTA tile 128x64, BK=32, 8 warps (32x32 each), 3-stage cp.async pipeline.
// DEST: 0 = Cout [M,D];  1/2 = g_Q/g_K (+RoPE, [B,H,S,DK]);  3 = g_V remap.
// ---------------------------------------------------------------------------
#define BM 128
#define BN 64
#define BK 32
#define KSTR 40                         // smem row stride in elements (80B)
#define SA_HI 0
#define SA_LO (BM*KSTR*2)               // 10240
#define SB_HI (2*BM*KSTR*2)             // 20480
#define SB_LO (2*BM*KSTR*2 + BN*KSTR*2) // 25600
#define STG_BYTES (2*BM*KSTR*2 + 2*BN*KSTR*2)  // 30720
#define NSTG 3
#define GEMM_SMEM (NSTG*STG_BYTES)      // 92160
#define NIT (D_/BK)                     // 32

template<int DEST>
__global__ __launch_bounds__(256)
void gemm_mma(const __nv_bfloat16* __restrict__ Ahi,
              const __nv_bfloat16* __restrict__ Alo,
              const __nv_bfloat16* __restrict__ Bhi,
              const __nv_bfloat16* __restrict__ Blo,
              float* __restrict__ Cout, const int* __restrict__ tokpos)
{
    extern __shared__ __align__(16) char smem[];
    const uint32_t sb = smem_u32(smem);
    const int tid  = threadIdx.x;
    const int lane = tid & 31, w = tid >> 5;
    const int wm = (w & 3) * 32;        // warp M offset in CTA tile
    const int wn = (w >> 2) * 32;       // warp N offset
    const int m0 = blockIdx.x * BM;
    const int n0 = blockIdx.y * BN;

    // per-thread load coords
    const int arow0 = tid >> 2,        acc4 = (tid & 3);          // A chunk 0
    const int arow1 = (tid + 256) >> 2;                            // A chunk 1
    const int brow  = tid >> 2;                                    // B chunk

    auto load_stage = [&](int st, int it) {
        const uint32_t s = sb + st * STG_BYTES;
        const int kk = it * BK;
        const size_t ga0 = (size_t)(m0 + arow0) * D_ + kk + acc4 * 8;
        const size_t ga1 = (size_t)(m0 + arow1) * D_ + kk + acc4 * 8;
        const uint32_t so0 = arow0 * 80 + acc4 * 16;
        const uint32_t so1 = arow1 * 80 + acc4 * 16;
        cp16(s + SA_HI + so0, Ahi + ga0);
        cp16(s + SA_HI + so1, Ahi + ga1);
        cp16(s + SA_LO + so0, Alo + ga0);
        cp16(s + SA_LO + so1, Alo + ga1);
        const size_t gb = (size_t)(n0 + brow) * D_ + kk + acc4 * 8;
        const uint32_t sob = brow * 80 + acc4 * 16;
        cp16(s + SB_HI + sob, Bhi + gb);
        cp16(s + SB_LO + sob, Blo + gb);
    };

    float acc[2][4][4];
#pragma unroll
    for (int mt = 0; mt < 2; mt++)
#pragma unroll
        for (int nt = 0; nt < 4; nt++)
#pragma unroll
            for (int r = 0; r < 4; r++) acc[mt][nt][r] = 0.f;

    load_stage(0, 0); CP_COMMIT();
    load_stage(1, 1); CP_COMMIT();

    // ldmatrix address components (byte offsets within a stage)
    const uint32_t a_row_off = (wm + (lane & 15)) * 80 + ((lane >> 4) << 4); // +16B for k-hi half
    const uint32_t b_row_off = (wn + (lane & 7)) * 80 + (((lane >> 3) & 1) << 4);

    for (int it = 0; it < NIT; it++) {
        CP_WAIT1();
        __syncthreads();
        if (it + 2 < NIT) load_stage((it + 2) % NSTG, it + 2);
        CP_COMMIT();

        const uint32_t s = sb + (it % NSTG) * STG_BYTES;
#pragma unroll
        for (int ks = 0; ks < 2; ks++) {         // two k16 steps in BK=32
            const uint32_t kofs = ks * 32;        // 16 elems = 32 bytes
            uint32_t a_hi[2][4], a_lo[2][4], b_hi[4][2], b_lo[4][2];
#pragma unroll
            for (int mt = 0; mt < 2; mt++) {
                const uint32_t ao = a_row_off + mt * 16 * 80 + kofs;
                ldmA(a_hi[mt], s + SA_HI + ao);
                ldmA(a_lo[mt], s + SA_LO + ao);
            }
#pragma unroll
            for (int nt = 0; nt < 4; nt++) {
                const uint32_t bo = b_row_off + nt * 8 * 80 + kofs;
                ldmB(b_hi[nt], s + SB_HI + bo);
                ldmB(b_lo[nt], s + SB_LO + bo);
            }
#pragma unroll
            for (int mt = 0; mt < 2; mt++)
#pragma unroll
                for (int nt = 0; nt < 4; nt++) {
                    mma_bf16(acc[mt][nt], a_hi[mt], b_hi[nt]);
                    mma_bf16(acc[mt][nt], a_hi[mt], b_lo[nt]);
                    mma_bf16(acc[mt][nt], a_lo[mt], b_hi[nt]);
                }
        }
        __syncthreads();
    }

    // ------------------------ epilogue ------------------------
    // thread holds C[r0][c], C[r0][c+1], C[r0+8][c], C[r0+8][c+1] per (mt,nt)
#pragma unroll
    for (int mt = 0; mt < 2; mt++) {
        const int r0 = m0 + wm + mt * 16 + (lane >> 2);
#pragma unroll
        for (int nt = 0; nt < 4; nt++) {
            const int ncol = n0 + wn + nt * 8 + (lane & 3) * 2;
            if (DEST == 0) {
                *(float2*)(Cout + (size_t)r0 * D_ + ncol) =
                    make_float2(acc[mt][nt][0], acc[mt][nt][1]);
                *(float2*)(Cout + (size_t)(r0 + 8) * D_ + ncol) =
                    make_float2(acc[mt][nt][2], acc[mt][nt][3]);
            } else if (DEST == 3) {
                const int h = ncol >> 6, dk = ncol & 63;
#pragma unroll
                for (int rr = 0; rr < 2; rr++) {
                    const int m = r0 + rr * 8;
                    const int bb = m >> 11, ss = m & (S_ - 1);
                    *(float2*)(g_V + (((size_t)(bb * H_ + h)) * S_ + ss) * DK_ + dk) =
                        make_float2(acc[mt][nt][2 * rr], acc[mt][nt][2 * rr + 1]);
                }
            } else {
                float* Dst = (DEST == 1) ? g_Q : g_K;
                const int h = ncol >> 6, dk = ncol & 63;   // dk even: RoPE pair
                const float fr = powf(10000.f, -(float)dk / 64.f);
#pragma unroll
                for (int rr = 0; rr < 2; rr++) {
                    const int m = r0 + rr * 8;
                    const int bb = m >> 11, ss = m & (S_ - 1);
                    const float pos = (float)tokpos[ss];
                    float sn, cs;
                    sincosf(pos * fr, &sn, &cs);
                    const float e  = acc[mt][nt][2 * rr];
                    const float od = acc[mt][nt][2 * rr + 1];
                    *(float2*)(Dst + (((size_t)(bb * H_ + h)) * S_ + ss) * DK_ + dk) =
                        make_float2(e * cs - od * sn, e * sn + od * cs);
                }
            }
        }
    }
}

// ---------------------------------------------------------------------------
// Flash attention (fp32, causal). Unchanged math from R1; writes bf16 hi/lo.
// ---------------------------------------------------------------------------
__global__ __launch_bounds__(256)
void attn_kernel()
{
    extern __shared__ __align__(16) float sm[];
    float (*Qs)[68] = (float(*)[68])(sm);
    float (*Ks)[68] = (float(*)[68])(sm + 1 * 64 * 68);
    float (*Vs)[68] = (float(*)[68])(sm + 2 * 64 * 68);
    float (*Ps)[68] = (float(*)[68])(sm + 3 * 64 * 68);

    const int tid = threadIdx.x;
    const int tx  = tid & 15;
    const int ty  = tid >> 4;
    const int qt  = (int)(gridDim.x - 1 - blockIdx.x);
    const int h   = blockIdx.y, b = blockIdx.z;
    const size_t base = ((size_t)(b * H_ + h)) * S_ * DK_;
    const int q0 = qt * 64;

#pragma unroll
    for (int i = 0; i < 4; i++) {
        int idx = tid + i * 256;
        int r = idx >> 4, c = (idx & 15) << 2;
        float4 v = *(const float4*)(g_Q + base + (size_t)(q0 + r) * DK_ + c);
        Qs[c+0][r] = v.x; Qs[c+1][r] = v.y; Qs[c+2][r] = v.z; Qs[c+3][r] = v.w;
    }

    float mi[4], li[4], o[4][4];
#pragma unroll
    for (int i = 0; i < 4; i++) {
        mi[i] = -1e30f; li[i] = 0.f;
#pragma unroll
        for (int j = 0; j < 4; j++) o[i][j] = 0.f;
    }

    for (int kt = 0; kt <= qt; kt++) {
        const int k0 = kt * 64;
        __syncthreads();
#pragma unroll
        for (int i = 0; i < 4; i++) {
            int idx = tid + i * 256;
            int r = idx >> 4, c = (idx & 15) << 2;
            float4 v = *(const float4*)(g_K + base + (size_t)(k0 + r) * DK_ + c);
            Ks[c+0][r] = v.x; Ks[c+1][r] = v.y; Ks[c+2][r] = v.z; Ks[c+3][r] = v.w;
            float4 w = *(const float4*)(g_V + base + (size_t)(k0 + r) * DK_ + c);
            *(float4*)(&Vs[r][c]) = w;
        }
        __syncthreads();

        float s[4][4];
#pragma unroll
        for (int i = 0; i < 4; i++)
#pragma unroll
            for (int j = 0; j < 4; j++) s[i][j] = 0.f;
#pragma unroll
        for (int d = 0; d < 64; d++) {
            float4 qv = *(const float4*)(&Qs[d][ty*4]);
            float4 kv = *(const float4*)(&Ks[d][tx*4]);
            float qa[4] = {qv.x, qv.y, qv.z, qv.w};
            float ka[4] = {kv.x, kv.y, kv.z, kv.w};
#pragma unroll
            for (int i = 0; i < 4; i++)
#pragma unroll
                for (int j = 0; j < 4; j++)
                    s[i][j] = fmaf(qa[i], ka[j], s[i][j]);
        }
#pragma unroll
        for (int i = 0; i < 4; i++)
#pragma unroll
            for (int j = 0; j < 4; j++) s[i][j] *= 0.125f;

        if (kt == qt) {
#pragma unroll
            for (int i = 0; i < 4; i++)
#pragma unroll
                for (int j = 0; j < 4; j++)
                    if (k0 + tx*4 + j > q0 + ty*4 + i) s[i][j] = -1e30f;
        }

#pragma unroll
        for (int i = 0; i < 4; i++) {
            float v = fmaxf(fmaxf(s[i][0], s[i][1]), fmaxf(s[i][2], s[i][3]));
            v = fmaxf(v, __shfl_xor_sync(0xffffffffu, v, 8));
            v = fmaxf(v, __shfl_xor_sync(0xffffffffu, v, 4));
            v = fmaxf(v, __shfl_xor_sync(0xffffffffu, v, 2));
            v = fmaxf(v, __shfl_xor_sync(0xffffffffu, v, 1));
            float mnew = fmaxf(mi[i], v);
            float corr = __expf(mi[i] - mnew);
            float rs = 0.f;
#pragma unroll
            for (int j = 0; j < 4; j++) { s[i][j] = __expf(s[i][j] - mnew); rs += s[i][j]; }
            rs += __shfl_xor_sync(0xffffffffu, rs, 8);
            rs += __shfl_xor_sync(0xffffffffu, rs, 4);
            rs += __shfl_xor_sync(0xffffffffu, rs, 2);
            rs += __shfl_xor_sync(0xffffffffu, rs, 1);
            li[i] = li[i] * corr + rs;
            mi[i] = mnew;
#pragma unroll
            for (int j = 0; j < 4; j++) o[i][j] *= corr;
        }

#pragma unroll
        for (int i = 0; i < 4; i++)
            *(float4*)(&Ps[ty*4 + i][tx*4]) =
                make_float4(s[i][0], s[i][1], s[i][2], s[i][3]);
        __syncthreads();

#pragma unroll 4
        for (int j = 0; j < 64; j++) {
            float4 vv = *(const float4*)(&Vs[j][tx*4]);
#pragma unroll
            for (int i = 0; i < 4; i++) {
                float p = Ps[ty*4 + i][j];
                o[i][0] = fmaf(p, vv.x, o[i][0]);
                o[i][1] = fmaf(p, vv.y, o[i][1]);
                o[i][2] = fmaf(p, vv.z, o[i][2]);
                o[i][3] = fmaf(p, vv.w, o[i][3]);
            }
        }
    }

#pragma unroll
    for (int i = 0; i < 4; i++) {
        int row = q0 + ty*4 + i;
        float inv = 1.f / li[i];
        size_t off = ((size_t)b * S_ + row) * D_ + h * DK_ + tx*4;
        float v0 = o[i][0]*inv, v1 = o[i][1]*inv, v2 = o[i][2]*inv, v3 = o[i][3]*inv;
        __nv_bfloat16 h0 = __float2bfloat16(v0), h1 = __float2bfloat16(v1);
        __nv_bfloat16 h2 = __float2bfloat16(v2), h3 = __float2bfloat16(v3);
        __nv_bfloat16 l0 = __float2bfloat16(v0 - __bfloat162float(h0));
        __nv_bfloat16 l1 = __float2bfloat16(v1 - __bfloat162float(h1));
        __nv_bfloat16 l2 = __float2bfloat16(v2 - __bfloat162float(h2));
        __nv_bfloat16 l3 = __float2bfloat16(v3 - __bfloat162float(h3));
        *(__nv_bfloat162*)(g_AOhi + off)     = __halves2bfloat162(h0, h1);
        *(__nv_bfloat162*)(g_AOhi + off + 2) = __halves2bfloat162(h2, h3);
        *(__nv_bfloat162*)(g_AOlo + off)     = __halves2bfloat162(l0, l1);
        *(__nv_bfloat162*)(g_AOlo + off + 2) = __halves2bfloat162(l2, l3);
    }
}

// ---------------------------------------------------------------------------
// Host
// ---------------------------------------------------------------------------
extern "C" void kernel_launch(void* const* d_in, const int* in_sizes, int n_in,
                              void* d_out, int out_size)
{
    const float* x  = (const float*)d_in[0];
    const float* qw = (const float*)d_in[1];
    const float* kw = (const float*)d_in[2];
    const float* vw = (const float*)d_in[3];
    const float* ow = (const float*)d_in[4];
    const int*   tp = (const int*)d_in[6];
    float* out = (float*)d_out;

    void *xhi, *xlo, *whi, *wlo, *aohi, *aolo;
    cudaGetSymbolAddress(&xhi,  g_Xhi);
    cudaGetSymbolAddress(&xlo,  g_Xlo);
    cudaGetSymbolAddress(&whi,  g_Whi);
    cudaGetSymbolAddress(&wlo,  g_Wlo);
    cudaGetSymbolAddress(&aohi, g_AOhi);
    cudaGetSymbolAddress(&aolo, g_AOlo);

    __nv_bfloat16* Xhi  = (__nv_bfloat16*)xhi;
    __nv_bfloat16* Xlo  = (__nv_bfloat16*)xlo;
    __nv_bfloat16* Whi  = (__nv_bfloat16*)whi;
    __nv_bfloat16* Wlo  = (__nv_bfloat16*)wlo;
    __nv_bfloat16* AOhi = (__nv_bfloat16*)aohi;
    __nv_bfloat16* AOlo = (__nv_bfloat16*)aolo;

    // Splits
    split_bf16<<<(M_*D_/4 + 255)/256, 256>>>(x, Xhi, Xlo, M_*D_);
    const float* ws[4] = {qw, kw, vw, ow};
    for (int i = 0; i < 4; i++)
        split_bf16<<<(D_*D_/4 + 255)/256, 256>>>(ws[i],
            Whi + (size_t)i * D_ * D_, Wlo + (size_t)i * D_ * D_, D_*D_);

    cudaFuncSetAttribute(gemm_mma<0>, cudaFuncAttributeMaxDynamicSharedMemorySize, GEMM_SMEM);
    cudaFuncSetAttribute(gemm_mma<1>, cudaFuncAttributeMaxDynamicSharedMemorySize, GEMM_SMEM);
    cudaFuncSetAttribute(gemm_mma<2>, cudaFuncAttributeMaxDynamicSharedMemorySize, GEMM_SMEM);
    cudaFuncSetAttribute(gemm_mma<3>, cudaFuncAttributeMaxDynamicSharedMemorySize, GEMM_SMEM);

    dim3 ggrid(M_ / BM, D_ / BN);   // (32, 16)
    gemm_mma<1><<<ggrid, 256, GEMM_SMEM>>>(Xhi, Xlo,
        Whi + 0 * (size_t)D_ * D_, Wlo + 0 * (size_t)D_ * D_, nullptr, tp);
    gemm_mma<2><<<ggrid, 256, GEMM_SMEM>>>(Xhi, Xlo,
        Whi + 1 * (size_t)D_ * D_, Wlo + 1 * (size_t)D_ * D_, nullptr, tp);
    gemm_mma<3><<<ggrid, 256, GEMM_SMEM>>>(Xhi, Xlo,
        Whi + 2 * (size_t)D_ * D_, Wlo + 2 * (size_t)D_ * D_, nullptr, tp);

    const int attn_smem = 4 * 64 * 68 * (int)sizeof(float);
    cudaFuncSetAttribute(attn_kernel, cudaFuncAttributeMaxDynamicSharedMemorySize, attn_smem);
    dim3 agrid(S_ / 64, H_, B_);
    attn_kernel<<<agrid, 256, attn_smem>>>();

    gemm_mma<0><<<ggrid, 256, GEMM_SMEM>>>(AOhi, AOlo,
        Whi + 3 * (size_t)D_ * D_, Wlo + 3 * (size_t)D_ * D_, out, tp);
}

// round 4
// speedup vs baseline: 2.4336x; 1.6073x over previous
#include <cuda_runtime.h>
#include <cuda_bf16.h>
#include <math.h>
#include <stdint.h>

#define B_  2
#define S_  2048
#define D_  1024
#define H_  16
#define DK_ 64
#define M_  (B_*S_)

// ---------------------------------------------------------------------------
// Scratch (__device__ globals; allocation-free contract)
// ---------------------------------------------------------------------------
__device__ __align__(16) __nv_bfloat16 g_Xhi[M_*D_];
__device__ __align__(16) __nv_bfloat16 g_Xlo[M_*D_];
__device__ __align__(16) __nv_bfloat16 g_Whi[4*(size_t)D_*D_];   // [mat][n][k]
__device__ __align__(16) __nv_bfloat16 g_Wlo[4*(size_t)D_*D_];
__device__ __align__(16) __nv_bfloat16 g_AOhi[M_*D_];
__device__ __align__(16) __nv_bfloat16 g_AOlo[M_*D_];
__device__ __align__(16) __nv_bfloat16 g_Qhi[B_*H_*S_*DK_];
__device__ __align__(16) __nv_bfloat16 g_Qlo[B_*H_*S_*DK_];
__device__ __align__(16) __nv_bfloat16 g_Khi[B_*H_*S_*DK_];
__device__ __align__(16) __nv_bfloat16 g_Klo[B_*H_*S_*DK_];
__device__ __align__(16) __nv_bfloat16 g_Vhi[B_*H_*S_*DK_];
__device__ __align__(16) __nv_bfloat16 g_Vlo[B_*H_*S_*DK_];

// ---------------------------------------------------------------------------
// PTX wrappers (arch-neutral sm_80-class)
// ---------------------------------------------------------------------------
__device__ __forceinline__ uint32_t smem_u32(const void* p) {
    uint32_t a;
    asm("{ .reg .u64 t; cvta.to.shared.u64 t, %1; cvt.u32.u64 %0, t; }"
        : "=r"(a) : "l"(p));
    return a;
}
__device__ __forceinline__ void cp16(uint32_t dst, const void* src) {
    asm volatile("cp.async.cg.shared.global [%0], [%1], 16;"
                 :: "r"(dst), "l"(src));
}
#define CP_COMMIT() asm volatile("cp.async.commit_group;")
#define CP_WAIT1()  asm volatile("cp.async.wait_group 1;")

__device__ __forceinline__ void ldmA(uint32_t (&a)[4], uint32_t addr) {
    asm volatile("ldmatrix.sync.aligned.m8n8.x4.shared.b16 {%0,%1,%2,%3}, [%4];"
                 : "=r"(a[0]), "=r"(a[1]), "=r"(a[2]), "=r"(a[3]) : "r"(addr));
}
__device__ __forceinline__ void ldmB(uint32_t (&b)[2], uint32_t addr) {
    asm volatile("ldmatrix.sync.aligned.m8n8.x2.shared.b16 {%0,%1}, [%2];"
                 : "=r"(b[0]), "=r"(b[1]) : "r"(addr));
}
__device__ __forceinline__ void ldmVT(uint32_t (&b)[2], uint32_t addr) {
    asm volatile("ldmatrix.sync.aligned.m8n8.x2.trans.shared.b16 {%0,%1}, [%2];"
                 : "=r"(b[0]), "=r"(b[1]) : "r"(addr));
}
__device__ __forceinline__ void mma_bf16(float (&d)[4], const uint32_t (&a)[4],
                                         const uint32_t (&b)[2]) {
    asm volatile(
        "mma.sync.aligned.m16n8k16.row.col.f32.bf16.bf16.f32 "
        "{%0,%1,%2,%3}, {%4,%5,%6,%7}, {%8,%9}, {%0,%1,%2,%3};"
        : "+f"(d[0]), "+f"(d[1]), "+f"(d[2]), "+f"(d[3])
        : "r"(a[0]), "r"(a[1]), "r"(a[2]), "r"(a[3]), "r"(b[0]), "r"(b[1]));
}
// pack2(a, b) -> bf16x2 with .lo = bf16(a), .hi = bf16(b)
__device__ __forceinline__ uint32_t pack2(float a, float b) {
    uint32_t r;
    asm("cvt.rn.bf16x2.f32 %0, %1, %2;" : "=r"(r) : "f"(b), "f"(a));
    return r;
}
__device__ __forceinline__ float ex2f(float x) {
    float y; asm("ex2.approx.f32 %0, %1;" : "=f"(y) : "f"(x)); return y;
}

// store fp32 pair as bf16 hi/lo pair
__device__ __forceinline__ void store_hilo(__nv_bfloat16* H, __nv_bfloat16* L,
                                           size_t idx, float v0, float v1) {
    uint32_t hi = pack2(v0, v1);
    float fh0 = __uint_as_float(hi << 16);
    float fh1 = __uint_as_float(hi & 0xffff0000u);
    uint32_t lo = pack2(v0 - fh0, v1 - fh1);
    *(uint32_t*)(H + idx) = hi;
    *(uint32_t*)(L + idx) = lo;
}

// ---------------------------------------------------------------------------
// fp32 -> bf16 (hi, lo) split
// ---------------------------------------------------------------------------
__global__ __launch_bounds__(256)
void split_bf16(const float* __restrict__ src, __nv_bfloat16* __restrict__ hi,
                __nv_bfloat16* __restrict__ lo, int n)
{
    int i = (blockIdx.x * blockDim.x + threadIdx.x) * 4;
    if (i >= n) return;
    float4 v = *(const float4*)(src + i);
    store_hilo(hi, lo, i,     v.x, v.y);
    store_hilo(hi, lo, i + 2, v.z, v.w);
}

// ---------------------------------------------------------------------------
// Split-bf16 tensor-core GEMM (C ≈ Ahi*Whi + Ahi*Wlo + Alo*Whi, fp32 accum)
// CTA 128x64, BK=32, 8 warps, 3-stage cp.async.
// DEST: 0 = Cout fp32 [M,D]; 1/2 = Q/K (+RoPE) bf16 hi/lo [B,H,S,DK];
//       3 = V bf16 hi/lo [B,H,S,DK].
// ---------------------------------------------------------------------------
#define BM 128
#define BN 64
#define BK 32
#define SA_HI 0
#define SA_LO (BM*80)
#define SB_HI (2*BM*80)
#define SB_LO (2*BM*80 + BN*80)
#define STG_BYTES (2*BM*80 + 2*BN*80)   // 30720
#define NSTG 3
#define GEMM_SMEM (NSTG*STG_BYTES)
#define NIT (D_/BK)

template<int DEST>
__global__ __launch_bounds__(256)
void gemm_mma(const __nv_bfloat16* __restrict__ Ahi,
              const __nv_bfloat16* __restrict__ Alo,
              const __nv_bfloat16* __restrict__ Bhi,
              const __nv_bfloat16* __restrict__ Blo,
              float* __restrict__ Cout, const int* __restrict__ tokpos)
{
    extern __shared__ __align__(16) char smem[];
    const uint32_t sb = smem_u32(smem);
    const int tid  = threadIdx.x;
    const int lane = tid & 31, w = tid >> 5;
    const int wm = (w & 3) * 32;
    const int wn = (w >> 2) * 32;
    const int m0 = blockIdx.x * BM;
    const int n0 = blockIdx.y * BN;

    const int arow0 = tid >> 2, acc4 = (tid & 3);
    const int arow1 = (tid + 256) >> 2;
    const int brow  = tid >> 2;

    auto load_stage = [&](int st, int it) {
        const uint32_t s = sb + st * STG_BYTES;
        const int kk = it * BK;
        const size_t ga0 = (size_t)(m0 + arow0) * D_ + kk + acc4 * 8;
        const size_t ga1 = (size_t)(m0 + arow1) * D_ + kk + acc4 * 8;
        const uint32_t so0 = arow0 * 80 + acc4 * 16;
        const uint32_t so1 = arow1 * 80 + acc4 * 16;
        cp16(s + SA_HI + so0, Ahi + ga0);
        cp16(s + SA_HI + so1, Ahi + ga1);
        cp16(s + SA_LO + so0, Alo + ga0);
        cp16(s + SA_LO + so1, Alo + ga1);
        const size_t gb = (size_t)(n0 + brow) * D_ + kk + acc4 * 8;
        const uint32_t sob = brow * 80 + acc4 * 16;
        cp16(s + SB_HI + sob, Bhi + gb);
        cp16(s + SB_LO + sob, Blo + gb);
    };

    float acc[2][4][4];
#pragma unroll
    for (int mt = 0; mt < 2; mt++)
#pragma unroll
        for (int nt = 0; nt < 4; nt++)
#pragma unroll
            for (int r = 0; r < 4; r++) acc[mt][nt][r] = 0.f;

    load_stage(0, 0); CP_COMMIT();
    load_stage(1, 1); CP_COMMIT();

    const uint32_t a_row_off = (wm + (lane & 15)) * 80 + ((lane >> 4) << 4);
    const uint32_t b_row_off = (wn + (lane & 7)) * 80 + (((lane >> 3) & 1) << 4);

    for (int it = 0; it < NIT; it++) {
        CP_WAIT1();
        __syncthreads();
        if (it + 2 < NIT) load_stage((it + 2) % NSTG, it + 2);
        CP_COMMIT();

        const uint32_t s = sb + (it % NSTG) * STG_BYTES;
#pragma unroll
        for (int ks = 0; ks < 2; ks++) {
            const uint32_t kofs = ks * 32;
            uint32_t a_hi[2][4], a_lo[2][4], b_hi[4][2], b_lo[4][2];
#pragma unroll
            for (int mt = 0; mt < 2; mt++) {
                const uint32_t ao = a_row_off + mt * 16 * 80 + kofs;
                ldmA(a_hi[mt], s + SA_HI + ao);
                ldmA(a_lo[mt], s + SA_LO + ao);
            }
#pragma unroll
            for (int nt = 0; nt < 4; nt++) {
                const uint32_t bo = b_row_off + nt * 8 * 80 + kofs;
                ldmB(b_hi[nt], s + SB_HI + bo);
                ldmB(b_lo[nt], s + SB_LO + bo);
            }
#pragma unroll
            for (int mt = 0; mt < 2; mt++)
#pragma unroll
                for (int nt = 0; nt < 4; nt++) {
                    mma_bf16(acc[mt][nt], a_hi[mt], b_hi[nt]);
                    mma_bf16(acc[mt][nt], a_hi[mt], b_lo[nt]);
                    mma_bf16(acc[mt][nt], a_lo[mt], b_hi[nt]);
                }
        }
        __syncthreads();
    }

#pragma unroll
    for (int mt = 0; mt < 2; mt++) {
        const int r0 = m0 + wm + mt * 16 + (lane >> 2);
#pragma unroll
        for (int nt = 0; nt < 4; nt++) {
            const int ncol = n0 + wn + nt * 8 + (lane & 3) * 2;
            if (DEST == 0) {
                *(float2*)(Cout + (size_t)r0 * D_ + ncol) =
                    make_float2(acc[mt][nt][0], acc[mt][nt][1]);
                *(float2*)(Cout + (size_t)(r0 + 8) * D_ + ncol) =
                    make_float2(acc[mt][nt][2], acc[mt][nt][3]);
            } else if (DEST == 3) {
                const int h = ncol >> 6, dk = ncol & 63;
#pragma unroll
                for (int rr = 0; rr < 2; rr++) {
                    const int m = r0 + rr * 8;
                    const int bb = m >> 11, ss = m & (S_ - 1);
                    size_t idx = (((size_t)(bb * H_ + h)) * S_ + ss) * DK_ + dk;
                    store_hilo(g_Vhi, g_Vlo, idx,
                               acc[mt][nt][2 * rr], acc[mt][nt][2 * rr + 1]);
                }
            } else {
                __nv_bfloat16* DH = (DEST == 1) ? g_Qhi : g_Khi;
                __nv_bfloat16* DL = (DEST == 1) ? g_Qlo : g_Klo;
                const int h = ncol >> 6, dk = ncol & 63;   // dk even: RoPE pair
                const float fr = powf(10000.f, -(float)dk / 64.f);
#pragma unroll
                for (int rr = 0; rr < 2; rr++) {
                    const int m = r0 + rr * 8;
                    const int bb = m >> 11, ss = m & (S_ - 1);
                    const float pos = (float)tokpos[ss];
                    float sn, cs;
                    sincosf(pos * fr, &sn, &cs);
                    const float e  = acc[mt][nt][2 * rr];
                    const float od = acc[mt][nt][2 * rr + 1];
                    size_t idx = (((size_t)(bb * H_ + h)) * S_ + ss) * DK_ + dk;
                    store_hilo(DH, DL, idx, e * cs - od * sn, e * sn + od * cs);
                }
            }
        }
    }
}

// ---------------------------------------------------------------------------
// Flash attention on HMMA, split-bf16 (3-pass) for both QK^T and PV.
// CTA = 64 q x 64 kv, 4 warps (16 q rows each). P stays in registers.
// ---------------------------------------------------------------------------
#define ROWB 144                        // 64 bf16 row padded to 144B
#define KV_STG 36864                    // 4 matrices * 64*144
#define S_KHI 0
#define S_KLO 9216
#define S_VHI 18432
#define S_VLO 27648
#define S_QHI (2*KV_STG)                // 73728
#define S_QLO (2*KV_STG + 9216)
#define ATT_SMEM (2*KV_STG + 2*9216)    // 92160

__global__ __launch_bounds__(128)
void attn_mma()
{
    extern __shared__ __align__(16) char smem[];
    const uint32_t sb = smem_u32(smem);
    const int tid = threadIdx.x;
    const int lane = tid & 31, w = tid >> 5;
    const int qt = (int)(gridDim.x - 1 - blockIdx.x);  // long rows first
    const int h  = blockIdx.y, b = blockIdx.z;
    const int q0 = qt * 64;
    const size_t gbase = ((size_t)(b * H_ + h)) * S_ * DK_;

    auto load_kv = [&](int st, int kt) {
        const size_t gk = gbase + (size_t)kt * 64 * DK_;
        const uint32_t s = sb + st * KV_STG;
#pragma unroll
        for (int i = 0; i < 4; i++) {
            int idx = tid + i * 128;           // 0..511
            int row = idx >> 3, ch = idx & 7;
            uint32_t so = row * ROWB + ch * 16;
            size_t go = gk + (size_t)row * DK_ + ch * 8;
            cp16(s + S_KHI + so, g_Khi + go);
            cp16(s + S_KLO + so, g_Klo + go);
            cp16(s + S_VHI + so, g_Vhi + go);
            cp16(s + S_VLO + so, g_Vlo + go);
        }
    };
    // Q tile (once)
    {
        const size_t gq = gbase + (size_t)q0 * DK_;
#pragma unroll
        for (int i = 0; i < 4; i++) {
            int idx = tid + i * 128;
            int row = idx >> 3, ch = idx & 7;
            uint32_t so = row * ROWB + ch * 16;
            size_t go = gq + (size_t)row * DK_ + ch * 8;
            cp16(sb + S_QHI + so, g_Qhi + go);
            cp16(sb + S_QLO + so, g_Qlo + go);
        }
    }
    load_kv(0, 0); CP_COMMIT();
    if (qt >= 1) load_kv(1, 1);
    CP_COMMIT();

    const uint32_t a_row_off = ((w * 16 + (lane & 15)) * ROWB) + ((lane >> 4) << 4);
    const uint32_t b_row_off = ((lane & 7) * ROWB) + (((lane >> 3) & 1) << 4);
    const uint32_t v_row_off = (lane & 15) * ROWB;

    const int row_lo = w * 16 + (lane >> 2);      // local q row of c0/c1
    const int colx   = 2 * (lane & 3);            // local col base within n-tile

    float o[8][4];
#pragma unroll
    for (int d = 0; d < 8; d++)
#pragma unroll
        for (int r = 0; r < 4; r++) o[d][r] = 0.f;
    float mi0 = -1e30f, mi1 = -1e30f, li0 = 0.f, li1 = 0.f;
    const float SC = 0.18033688011112042f;   // log2(e)/8

    for (int kt = 0; kt <= qt; kt++) {
        CP_WAIT1();
        __syncthreads();
        const uint32_t kv = sb + (kt & 1) * KV_STG;

        // ---- S = Q K^T (3-pass split) ----
        float s[8][4];
#pragma unroll
        for (int nt = 0; nt < 8; nt++)
#pragma unroll
            for (int r = 0; r < 4; r++) s[nt][r] = 0.f;
#pragma unroll
        for (int ks = 0; ks < 4; ks++) {
            uint32_t qh[4], ql[4];
            ldmA(qh, sb + S_QHI + a_row_off + ks * 32);
            ldmA(ql, sb + S_QLO + a_row_off + ks * 32);
#pragma unroll
            for (int nt = 0; nt < 8; nt++) {
                uint32_t kh[2], kl[2];
                const uint32_t bo = b_row_off + nt * 8 * ROWB + ks * 32;
                ldmB(kh, kv + S_KHI + bo);
                ldmB(kl, kv + S_KLO + bo);
                mma_bf16(s[nt], qh, kh);
                mma_bf16(s[nt], qh, kl);
                mma_bf16(s[nt], ql, kh);
            }
        }
        // scale to base-2 domain
#pragma unroll
        for (int nt = 0; nt < 8; nt++)
#pragma unroll
            for (int r = 0; r < 4; r++) s[nt][r] *= SC;

        if (kt == qt) {    // causal mask (diag tile; q0 == k0)
#pragma unroll
            for (int nt = 0; nt < 8; nt++) {
                const int c = nt * 8 + colx;
                if (c     > row_lo)     s[nt][0] = -1e30f;
                if (c + 1 > row_lo)     s[nt][1] = -1e30f;
                if (c     > row_lo + 8) s[nt][2] = -1e30f;
                if (c + 1 > row_lo + 8) s[nt][3] = -1e30f;
            }
        }

        // ---- online softmax ----
        float r0 = -1e30f, r1 = -1e30f;
#pragma unroll
        for (int nt = 0; nt < 8; nt++) {
            r0 = fmaxf(r0, fmaxf(s[nt][0], s[nt][1]));
            r1 = fmaxf(r1, fmaxf(s[nt][2], s[nt][3]));
        }
        r0 = fmaxf(r0, __shfl_xor_sync(0xffffffffu, r0, 1));
        r0 = fmaxf(r0, __shfl_xor_sync(0xffffffffu, r0, 2));
        r1 = fmaxf(r1, __shfl_xor_sync(0xffffffffu, r1, 1));
        r1 = fmaxf(r1, __shfl_xor_sync(0xffffffffu, r1, 2));
        const float mn0 = fmaxf(mi0, r0), mn1 = fmaxf(mi1, r1);
        const float c0 = ex2f(mi0 - mn0), c1 = ex2f(mi1 - mn1);
        float sum0 = 0.f, sum1 = 0.f;
#pragma unroll
        for (int nt = 0; nt < 8; nt++) {
            s[nt][0] = ex2f(s[nt][0] - mn0);
            s[nt][1] = ex2f(s[nt][1] - mn0);
            s[nt][2] = ex2f(s[nt][2] - mn1);
            s[nt][3] = ex2f(s[nt][3] - mn1);
            sum0 += s[nt][0] + s[nt][1];
            sum1 += s[nt][2] + s[nt][3];
        }
        sum0 += __shfl_xor_sync(0xffffffffu, sum0, 1);
        sum0 += __shfl_xor_sync(0xffffffffu, sum0, 2);
        sum1 += __shfl_xor_sync(0xffffffffu, sum1, 1);
        sum1 += __shfl_xor_sync(0xffffffffu, sum1, 2);
        li0 = li0 * c0 + sum0; li1 = li1 * c1 + sum1;
        mi0 = mn0; mi1 = mn1;
#pragma unroll
        for (int d = 0; d < 8; d++) {
            o[d][0] *= c0; o[d][1] *= c0; o[d][2] *= c1; o[d][3] *= c1;
        }

        // ---- pack P into A-fragments (hi + lo) ----
        uint32_t ahi[4][4], alo[4][4];
#pragma unroll
        for (int kvs = 0; kvs < 4; kvs++) {
            const int j0 = 2 * kvs, j1 = 2 * kvs + 1;
            const float* p0 = s[j0];
            const float* p1 = s[j1];
            ahi[kvs][0] = pack2(p0[0], p0[1]);
            ahi[kvs][1] = pack2(p0[2], p0[3]);
            ahi[kvs][2] = pack2(p1[0], p1[1]);
            ahi[kvs][3] = pack2(p1[2], p1[3]);
#pragma unroll
            for (int q = 0; q < 4; q++) {
                const float* pp = (q < 2) ? p0 : p1;
                const int base = (q & 1) * 2;
                const uint32_t hreg = ahi[kvs][q];
                float f0 = __uint_as_float(hreg << 16);
                float f1 = __uint_as_float(hreg & 0xffff0000u);
                alo[kvs][q] = pack2(pp[base] - f0, pp[base + 1] - f1);
            }
        }

        // ---- O += P V (3-pass) ----
#pragma unroll
        for (int kvs = 0; kvs < 4; kvs++) {
#pragma unroll
            for (int d = 0; d < 8; d++) {
                uint32_t vh[2], vl[2];
                const uint32_t vo = (16 * kvs) * ROWB + v_row_off + d * 16;
                ldmVT(vh, kv + S_VHI + vo);
                ldmVT(vl, kv + S_VLO + vo);
                mma_bf16(o[d], ahi[kvs], vh);
                mma_bf16(o[d], alo[kvs], vh);
                mma_bf16(o[d], ahi[kvs], vl);
            }
        }

        __syncthreads();
        if (kt + 2 <= qt) load_kv(kt & 1, kt + 2);
        CP_COMMIT();
    }

    // ---- epilogue: normalize, write bf16 hi/lo [B,S,H*DK] ----
    const float inv0 = 1.f / li0, inv1 = 1.f / li1;
    const int grow0 = q0 + row_lo;
#pragma unroll
    for (int d = 0; d < 8; d++) {
        const int col = h * 64 + d * 8 + colx;
        size_t i0 = ((size_t)b * S_ + grow0) * D_ + col;
        size_t i1 = ((size_t)b * S_ + grow0 + 8) * D_ + col;
        store_hilo(g_AOhi, g_AOlo, i0, o[d][0] * inv0, o[d][1] * inv0);
        store_hilo(g_AOhi, g_AOlo, i1, o[d][2] * inv1, o[d][3] * inv1);
    }
}

// ---------------------------------------------------------------------------
// Host
// ---------------------------------------------------------------------------
extern "C" void kernel_launch(void* const* d_in, const int* in_sizes, int n_in,
                              void* d_out, int out_size)
{
    const float* x  = (const float*)d_in[0];
    const float* qw = (const float*)d_in[1];
    const float* kw = (const float*)d_in[2];
    const float* vw = (const float*)d_in[3];
    const float* ow = (const float*)d_in[4];
    const int*   tp = (const int*)d_in[6];
    float* out = (float*)d_out;

    void *xhi, *xlo, *whi, *wlo, *aohi, *aolo;
    cudaGetSymbolAddress(&xhi,  g_Xhi);
    cudaGetSymbolAddress(&xlo,  g_Xlo);
    cudaGetSymbolAddress(&whi,  g_Whi);
    cudaGetSymbolAddress(&wlo,  g_Wlo);
    cudaGetSymbolAddress(&aohi, g_AOhi);
    cudaGetSymbolAddress(&aolo, g_AOlo);

    __nv_bfloat16* Xhi  = (__nv_bfloat16*)xhi;
    __nv_bfloat16* Xlo  = (__nv_bfloat16*)xlo;
    __nv_bfloat16* Whi  = (__nv_bfloat16*)whi;
    __nv_bfloat16* Wlo  = (__nv_bfloat16*)wlo;
    __nv_bfloat16* AOhi = (__nv_bfloat16*)aohi;
    __nv_bfloat16* AOlo = (__nv_bfloat16*)aolo;

    split_bf16<<<(M_*D_/4 + 255)/256, 256>>>(x, Xhi, Xlo, M_*D_);
    const float* ws[4] = {qw, kw, vw, ow};
    for (int i = 0; i < 4; i++)
        split_bf16<<<(D_*D_/4 + 255)/256, 256>>>(ws[i],
            Whi + (size_t)i * D_ * D_, Wlo + (size_t)i * D_ * D_, D_*D_);

    cudaFuncSetAttribute(gemm_mma<0>, cudaFuncAttributeMaxDynamicSharedMemorySize, GEMM_SMEM);
    cudaFuncSetAttribute(gemm_mma<1>, cudaFuncAttributeMaxDynamicSharedMemorySize, GEMM_SMEM);
    cudaFuncSetAttribute(gemm_mma<2>, cudaFuncAttributeMaxDynamicSharedMemorySize, GEMM_SMEM);
    cudaFuncSetAttribute(gemm_mma<3>, cudaFuncAttributeMaxDynamicSharedMemorySize, GEMM_SMEM);

    dim3 ggrid(M_ / BM, D_ / BN);   // (32, 16)
    gemm_mma<1><<<ggrid, 256, GEMM_SMEM>>>(Xhi, Xlo,
        Whi + 0 * (size_t)D_ * D_, Wlo + 0 * (size_t)D_ * D_, nullptr, tp);
    gemm_mma<2><<<ggrid, 256, GEMM_SMEM>>>(Xhi, Xlo,
        Whi + 1 * (size_t)D_ * D_, Wlo + 1 * (size_t)D_ * D_, nullptr, tp);
    gemm_mma<3><<<ggrid, 256, GEMM_SMEM>>>(Xhi, Xlo,
        Whi + 2 * (size_t)D_ * D_, Wlo + 2 * (size_t)D_ * D_, nullptr, tp);

    cudaFuncSetAttribute(attn_mma, cudaFuncAttributeMaxDynamicSharedMemorySize, ATT_SMEM);
    dim3 agrid(S_ / 64, H_, B_);    // (32, 16, 2)
    attn_mma<<<agrid, 128, ATT_SMEM>>>();

    gemm_mma<0><<<ggrid, 256, GEMM_SMEM>>>(AOhi, AOlo,
        Whi + 3 * (size_t)D_ * D_, Wlo + 3 * (size_t)D_ * D_, out, tp);
}

// round 5
// speedup vs baseline: 2.6104x; 1.0726x over previous
#include <cuda_runtime.h>
#include <cuda_bf16.h>
#include <math.h>
#include <stdint.h>

#define B_  2
#define S_  2048
#define D_  1024
#define H_  16
#define DK_ 64
#define M_  (B_*S_)

// ---------------------------------------------------------------------------
// Scratch (__device__ globals; allocation-free contract)
// ---------------------------------------------------------------------------
__device__ __align__(16) __nv_bfloat16 g_Xhi[M_*D_];
__device__ __align__(16) __nv_bfloat16 g_Xlo[M_*D_];
__device__ __align__(16) float         g_Xt [M_*D_];            // tf32-rounded
__device__ __align__(16) __nv_bfloat16 g_Whi[2*(size_t)D_*D_];  // q,k weights
__device__ __align__(16) __nv_bfloat16 g_Wlo[2*(size_t)D_*D_];
__device__ __align__(16) float         g_Wt [2*(size_t)D_*D_];  // v,o weights
__device__ __align__(16) float         g_AOt[M_*D_];            // attn out (tf32)
__device__ __align__(16) __nv_bfloat16 g_Qhi[B_*H_*S_*DK_];
__device__ __align__(16) __nv_bfloat16 g_Qlo[B_*H_*S_*DK_];
__device__ __align__(16) __nv_bfloat16 g_Khi[B_*H_*S_*DK_];
__device__ __align__(16) __nv_bfloat16 g_Klo[B_*H_*S_*DK_];
__device__ __align__(16) __nv_bfloat16 g_Vhi[B_*H_*S_*DK_];
__device__ __align__(16) __nv_bfloat16 g_Vlo[B_*H_*S_*DK_];

// ---------------------------------------------------------------------------
// PTX wrappers (arch-neutral sm_80-class)
// ---------------------------------------------------------------------------
__device__ __forceinline__ uint32_t smem_u32(const void* p) {
    uint32_t a;
    asm("{ .reg .u64 t; cvta.to.shared.u64 t, %1; cvt.u32.u64 %0, t; }"
        : "=r"(a) : "l"(p));
    return a;
}
__device__ __forceinline__ void cp16(uint32_t dst, const void* src) {
    asm volatile("cp.async.cg.shared.global [%0], [%1], 16;"
                 :: "r"(dst), "l"(src));
}
#define CP_COMMIT() asm volatile("cp.async.commit_group;")
#define CP_WAIT1()  asm volatile("cp.async.wait_group 1;")

__device__ __forceinline__ void ldmA(uint32_t (&a)[4], uint32_t addr) {
    asm volatile("ldmatrix.sync.aligned.m8n8.x4.shared.b16 {%0,%1,%2,%3}, [%4];"
                 : "=r"(a[0]), "=r"(a[1]), "=r"(a[2]), "=r"(a[3]) : "r"(addr));
}
__device__ __forceinline__ void ldmB(uint32_t (&b)[2], uint32_t addr) {
    asm volatile("ldmatrix.sync.aligned.m8n8.x2.shared.b16 {%0,%1}, [%2];"
                 : "=r"(b[0]), "=r"(b[1]) : "r"(addr));
}
__device__ __forceinline__ void ldmVT(uint32_t (&b)[2], uint32_t addr) {
    asm volatile("ldmatrix.sync.aligned.m8n8.x2.trans.shared.b16 {%0,%1}, [%2];"
                 : "=r"(b[0]), "=r"(b[1]) : "r"(addr));
}
__device__ __forceinline__ void mma_bf16(float (&d)[4], const uint32_t (&a)[4],
                                         const uint32_t (&b)[2]) {
    asm volatile(
        "mma.sync.aligned.m16n8k16.row.col.f32.bf16.bf16.f32 "
        "{%0,%1,%2,%3}, {%4,%5,%6,%7}, {%8,%9}, {%0,%1,%2,%3};"
        : "+f"(d[0]), "+f"(d[1]), "+f"(d[2]), "+f"(d[3])
        : "r"(a[0]), "r"(a[1]), "r"(a[2]), "r"(a[3]), "r"(b[0]), "r"(b[1]));
}
__device__ __forceinline__ void mma_tf32(float (&d)[4], const uint32_t (&a)[4],
                                         uint32_t b0, uint32_t b1) {
    asm volatile(
        "mma.sync.aligned.m16n8k8.row.col.f32.tf32.tf32.f32 "
        "{%0,%1,%2,%3}, {%4,%5,%6,%7}, {%8,%9}, {%0,%1,%2,%3};"
        : "+f"(d[0]), "+f"(d[1]), "+f"(d[2]), "+f"(d[3])
        : "r"(a[0]), "r"(a[1]), "r"(a[2]), "r"(a[3]), "r"(b0), "r"(b1));
}
__device__ __forceinline__ uint32_t pack2(float a, float b) {
    uint32_t r;
    asm("cvt.rn.bf16x2.f32 %0, %1, %2;" : "=r"(r) : "f"(b), "f"(a));
    return r;
}
__device__ __forceinline__ float ex2f(float x) {
    float y; asm("ex2.approx.f32 %0, %1;" : "=f"(y) : "f"(x)); return y;
}
__device__ __forceinline__ float tf32r(float x) {
    uint32_t r; asm("cvt.rna.tf32.f32 %0, %1;" : "=r"(r) : "f"(x));
    return __uint_as_float(r);
}
__device__ __forceinline__ void store_hilo(__nv_bfloat16* H, __nv_bfloat16* L,
                                           size_t idx, float v0, float v1) {
    uint32_t hi = pack2(v0, v1);
    float fh0 = __uint_as_float(hi << 16);
    float fh1 = __uint_as_float(hi & 0xffff0000u);
    uint32_t lo = pack2(v0 - fh0, v1 - fh1);
    *(uint32_t*)(H + idx) = hi;
    *(uint32_t*)(L + idx) = lo;
}

// ---------------------------------------------------------------------------
// Prep kernels
// ---------------------------------------------------------------------------
__global__ __launch_bounds__(256)
void prep_x(const float* __restrict__ src, __nv_bfloat16* __restrict__ hi,
            __nv_bfloat16* __restrict__ lo, float* __restrict__ t, int n)
{
    int i = (blockIdx.x * blockDim.x + threadIdx.x) * 4;
    if (i >= n) return;
    float4 v = *(const float4*)(src + i);
    store_hilo(hi, lo, i,     v.x, v.y);
    store_hilo(hi, lo, i + 2, v.z, v.w);
    *(float4*)(t + i) = make_float4(tf32r(v.x), tf32r(v.y), tf32r(v.z), tf32r(v.w));
}
__global__ __launch_bounds__(256)
void split_bf16(const float* __restrict__ src, __nv_bfloat16* __restrict__ hi,
                __nv_bfloat16* __restrict__ lo, int n)
{
    int i = (blockIdx.x * blockDim.x + threadIdx.x) * 4;
    if (i >= n) return;
    float4 v = *(const float4*)(src + i);
    store_hilo(hi, lo, i,     v.x, v.y);
    store_hilo(hi, lo, i + 2, v.z, v.w);
}
__global__ __launch_bounds__(256)
void conv_tf32(const float* __restrict__ src, float* __restrict__ dst, int n)
{
    int i = (blockIdx.x * blockDim.x + threadIdx.x) * 4;
    if (i >= n) return;
    float4 v = *(const float4*)(src + i);
    *(float4*)(dst + i) = make_float4(tf32r(v.x), tf32r(v.y), tf32r(v.z), tf32r(v.w));
}

// ---------------------------------------------------------------------------
// Split-bf16 GEMM (3-pass, HMMA). DEST: 1 = Q (+RoPE), 2 = K (+RoPE).
// CTA 128x64, BK=32, 8 warps, 3-stage cp.async.
// ---------------------------------------------------------------------------
#define BM 128
#define BN 64
#define BK 32
#define SA_HI 0
#define SA_LO (BM*80)
#define SB_HI (2*BM*80)
#define SB_LO (2*BM*80 + BN*80)
#define STG_BYTES (2*BM*80 + 2*BN*80)   // 30720
#define GEMM_SMEM (3*STG_BYTES)
#define NIT (D_/BK)

template<int DEST>
__global__ __launch_bounds__(256)
void gemm_mma(const __nv_bfloat16* __restrict__ Ahi,
              const __nv_bfloat16* __restrict__ Alo,
              const __nv_bfloat16* __restrict__ Bhi,
              const __nv_bfloat16* __restrict__ Blo,
              const int* __restrict__ tokpos)
{
    extern __shared__ __align__(16) char smem[];
    const uint32_t sb = smem_u32(smem);
    const int tid  = threadIdx.x;
    const int lane = tid & 31, w = tid >> 5;
    const int wm = (w & 3) * 32;
    const int wn = (w >> 2) * 32;
    const int m0 = blockIdx.x * BM;
    const int n0 = blockIdx.y * BN;

    const int arow0 = tid >> 2, acc4 = (tid & 3);
    const int arow1 = (tid + 256) >> 2;
    const int brow  = tid >> 2;

    auto load_stage = [&](int st, int it) {
        const uint32_t s = sb + st * STG_BYTES;
        const int kk = it * BK;
        const size_t ga0 = (size_t)(m0 + arow0) * D_ + kk + acc4 * 8;
        const size_t ga1 = (size_t)(m0 + arow1) * D_ + kk + acc4 * 8;
        const uint32_t so0 = arow0 * 80 + acc4 * 16;
        const uint32_t so1 = arow1 * 80 + acc4 * 16;
        cp16(s + SA_HI + so0, Ahi + ga0);
        cp16(s + SA_HI + so1, Ahi + ga1);
        cp16(s + SA_LO + so0, Alo + ga0);
        cp16(s + SA_LO + so1, Alo + ga1);
        const size_t gb = (size_t)(n0 + brow) * D_ + kk + acc4 * 8;
        const uint32_t sob = brow * 80 + acc4 * 16;
        cp16(s + SB_HI + sob, Bhi + gb);
        cp16(s + SB_LO + sob, Blo + gb);
    };

    float acc[2][4][4];
#pragma unroll
    for (int mt = 0; mt < 2; mt++)
#pragma unroll
        for (int nt = 0; nt < 4; nt++)
#pragma unroll
            for (int r = 0; r < 4; r++) acc[mt][nt][r] = 0.f;

    load_stage(0, 0); CP_COMMIT();
    load_stage(1, 1); CP_COMMIT();

    const uint32_t a_row_off = (wm + (lane & 15)) * 80 + ((lane >> 4) << 4);
    const uint32_t b_row_off = (wn + (lane & 7)) * 80 + (((lane >> 3) & 1) << 4);

    for (int it = 0; it < NIT; it++) {
        CP_WAIT1();
        __syncthreads();
        if (it + 2 < NIT) load_stage((it + 2) % 3, it + 2);
        CP_COMMIT();

        const uint32_t s = sb + (it % 3) * STG_BYTES;
#pragma unroll
        for (int ks = 0; ks < 2; ks++) {
            const uint32_t kofs = ks * 32;
            uint32_t a_hi[2][4], a_lo[2][4], b_hi[4][2], b_lo[4][2];
#pragma unroll
            for (int mt = 0; mt < 2; mt++) {
                const uint32_t ao = a_row_off + mt * 16 * 80 + kofs;
                ldmA(a_hi[mt], s + SA_HI + ao);
                ldmA(a_lo[mt], s + SA_LO + ao);
            }
#pragma unroll
            for (int nt = 0; nt < 4; nt++) {
                const uint32_t bo = b_row_off + nt * 8 * 80 + kofs;
                ldmB(b_hi[nt], s + SB_HI + bo);
                ldmB(b_lo[nt], s + SB_LO + bo);
            }
#pragma unroll
            for (int mt = 0; mt < 2; mt++)
#pragma unroll
                for (int nt = 0; nt < 4; nt++) {
                    mma_bf16(acc[mt][nt], a_hi[mt], b_hi[nt]);
                    mma_bf16(acc[mt][nt], a_hi[mt], b_lo[nt]);
                    mma_bf16(acc[mt][nt], a_lo[mt], b_hi[nt]);
                }
        }
        // no trailing sync: top-of-iter barrier orders stage reuse
    }

#pragma unroll
    for (int mt = 0; mt < 2; mt++) {
        const int r0 = m0 + wm + mt * 16 + (lane >> 2);
#pragma unroll
        for (int nt = 0; nt < 4; nt++) {
            const int ncol = n0 + wn + nt * 8 + (lane & 3) * 2;
            __nv_bfloat16* DH = (DEST == 1) ? g_Qhi : g_Khi;
            __nv_bfloat16* DL = (DEST == 1) ? g_Qlo : g_Klo;
            const int h = ncol >> 6, dk = ncol & 63;   // dk even: RoPE pair
            const float fr = powf(10000.f, -(float)dk / 64.f);
#pragma unroll
            for (int rr = 0; rr < 2; rr++) {
                const int m = r0 + rr * 8;
                const int bb = m >> 11, ss = m & (S_ - 1);
                const float pos = (float)tokpos[ss];
                float sn, cs;
                sincosf(pos * fr, &sn, &cs);
                const float e  = acc[mt][nt][2 * rr];
                const float od = acc[mt][nt][2 * rr + 1];
                size_t idx = (((size_t)(bb * H_ + h)) * S_ + ss) * DK_ + dk;
                store_hilo(DH, DL, idx, e * cs - od * sn, e * sn + od * cs);
            }
        }
    }
}

// ---------------------------------------------------------------------------
// Single-pass tf32 GEMM (m16n8k8). DEST: 0 = fp32 out; 3 = V bf16 hi/lo remap.
// CTA 128x64, BK=32, 8 warps, 3-stage cp.async. fp32 smem, 36-float row pad.
// ---------------------------------------------------------------------------
#define TROW 36
#define TSB_OFF (BM*TROW)                       // floats
#define TSTG ((BM*TROW + BN*TROW)*4)            // 27648 bytes
#define TSMEM (3*TSTG)                          // 82944

template<int DEST>
__global__ __launch_bounds__(256)
void gemm_tf32(const float* __restrict__ A, const float* __restrict__ W,
               float* __restrict__ Cout)
{
    extern __shared__ __align__(16) char smem[];
    const int tid  = threadIdx.x;
    const int lane = tid & 31, w = tid >> 5;
    const int wm = (w & 3) * 32;
    const int wn = (w >> 2) * 32;
    const int m0 = blockIdx.x * BM;
    const int n0 = blockIdx.y * BN;
    const int rg = lane >> 2, tc = lane & 3;

    auto load_stage = [&](int st, int it) {
        float* s = (float*)(smem + st * TSTG);
        const int kk = it * BK;
#pragma unroll
        for (int i = 0; i < 4; i++) {           // A: 128 rows x 8 chunks
            int idx = tid + i * 256;
            int row = idx >> 3, ch = idx & 7;
            cp16(smem_u32(s + row * TROW + ch * 4),
                 A + (size_t)(m0 + row) * D_ + kk + ch * 4);
        }
        float* sB = s + TSB_OFF;
#pragma unroll
        for (int i = 0; i < 2; i++) {           // B: 64 rows x 8 chunks
            int idx = tid + i * 256;
            int row = idx >> 3, ch = idx & 7;
            cp16(smem_u32(sB + row * TROW + ch * 4),
                 W + (size_t)(n0 + row) * D_ + kk + ch * 4);
        }
    };

    float acc[2][4][4];
#pragma unroll
    for (int mt = 0; mt < 2; mt++)
#pragma unroll
        for (int nt = 0; nt < 4; nt++)
#pragma unroll
            for (int r = 0; r < 4; r++) acc[mt][nt][r] = 0.f;

    load_stage(0, 0); CP_COMMIT();
    load_stage(1, 1); CP_COMMIT();

    for (int it = 0; it < NIT; it++) {
        CP_WAIT1();
        __syncthreads();
        if (it + 2 < NIT) load_stage((it + 2) % 3, it + 2);
        CP_COMMIT();

        const uint32_t* s  = (const uint32_t*)(smem + (it % 3) * TSTG);
        const uint32_t* sB = s + TSB_OFF;
#pragma unroll
        for (int ks = 0; ks < 4; ks++) {
            uint32_t a[2][4];
#pragma unroll
            for (int mt = 0; mt < 2; mt++) {
                const uint32_t* base = s + (wm + mt * 16 + rg) * TROW + ks * 8 + tc;
                a[mt][0] = base[0];
                a[mt][1] = base[8 * TROW];
                a[mt][2] = base[4];
                a[mt][3] = base[8 * TROW + 4];
            }
#pragma unroll
            for (int nt = 0; nt < 4; nt++) {
                const uint32_t* bp = sB + (wn + nt * 8 + rg) * TROW + ks * 8 + tc;
                const uint32_t b0 = bp[0], b1 = bp[4];
#pragma unroll
                for (int mt = 0; mt < 2; mt++)
                    mma_tf32(acc[mt][nt], a[mt], b0, b1);
            }
        }
    }

#pragma unroll
    for (int mt = 0; mt < 2; mt++) {
        const int r0 = m0 + wm + mt * 16 + (lane >> 2);
#pragma unroll
        for (int nt = 0; nt < 4; nt++) {
            const int ncol = n0 + wn + nt * 8 + (lane & 3) * 2;
            if (DEST == 0) {
                *(float2*)(Cout + (size_t)r0 * D_ + ncol) =
                    make_float2(acc[mt][nt][0], acc[mt][nt][1]);
                *(float2*)(Cout + (size_t)(r0 + 8) * D_ + ncol) =
                    make_float2(acc[mt][nt][2], acc[mt][nt][3]);
            } else {
                const int h = ncol >> 6, dk = ncol & 63;
#pragma unroll
                for (int rr = 0; rr < 2; rr++) {
                    const int m = r0 + rr * 8;
                    const int bb = m >> 11, ss = m & (S_ - 1);
                    size_t idx = (((size_t)(bb * H_ + h)) * S_ + ss) * DK_ + dk;
                    store_hilo(g_Vhi, g_Vlo, idx,
                               acc[mt][nt][2 * rr], acc[mt][nt][2 * rr + 1]);
                }
            }
        }
    }
}

// ---------------------------------------------------------------------------
// Flash attention on HMMA, split-bf16 3-pass QK^T and PV. Output -> g_AOt.
// ---------------------------------------------------------------------------
#define ROWB 144
#define KV_STG 36864
#define S_KHI 0
#define S_KLO 9216
#define S_VHI 18432
#define S_VLO 27648
#define S_QHI (2*KV_STG)
#define S_QLO (2*KV_STG + 9216)
#define ATT_SMEM (2*KV_STG + 2*9216)

__global__ __launch_bounds__(128)
void attn_mma()
{
    extern __shared__ __align__(16) char smem[];
    const uint32_t sb = smem_u32(smem);
    const int tid = threadIdx.x;
    const int lane = tid & 31, w = tid >> 5;
    const int qt = (int)(gridDim.x - 1 - blockIdx.x);
    const int h  = blockIdx.y, b = blockIdx.z;
    const int q0 = qt * 64;
    const size_t gbase = ((size_t)(b * H_ + h)) * S_ * DK_;

    auto load_kv = [&](int st, int kt) {
        const size_t gk = gbase + (size_t)kt * 64 * DK_;
        const uint32_t s = sb + st * KV_STG;
#pragma unroll
        for (int i = 0; i < 4; i++) {
            int idx = tid + i * 128;
            int row = idx >> 3, ch = idx & 7;
            uint32_t so = row * ROWB + ch * 16;
            size_t go = gk + (size_t)row * DK_ + ch * 8;
            cp16(s + S_KHI + so, g_Khi + go);
            cp16(s + S_KLO + so, g_Klo + go);
            cp16(s + S_VHI + so, g_Vhi + go);
            cp16(s + S_VLO + so, g_Vlo + go);
        }
    };
    {
        const size_t gq = gbase + (size_t)q0 * DK_;
#pragma unroll
        for (int i = 0; i < 4; i++) {
            int idx = tid + i * 128;
            int row = idx >> 3, ch = idx & 7;
            uint32_t so = row * ROWB + ch * 16;
            size_t go = gq + (size_t)row * DK_ + ch * 8;
            cp16(sb + S_QHI + so, g_Qhi + go);
            cp16(sb + S_QLO + so, g_Qlo + go);
        }
    }
    load_kv(0, 0); CP_COMMIT();
    if (qt >= 1) load_kv(1, 1);
    CP_COMMIT();

    const uint32_t a_row_off = ((w * 16 + (lane & 15)) * ROWB) + ((lane >> 4) << 4);
    const uint32_t b_row_off = ((lane & 7) * ROWB) + (((lane >> 3) & 1) << 4);
    const uint32_t v_row_off = (lane & 15) * ROWB;

    const int row_lo = w * 16 + (lane >> 2);
    const int colx   = 2 * (lane & 3);

    float o[8][4];
#pragma unroll
    for (int d = 0; d < 8; d++)
#pragma unroll
        for (int r = 0; r < 4; r++) o[d][r] = 0.f;
    float mi0 = -1e30f, mi1 = -1e30f, li0 = 0.f, li1 = 0.f;
    const float SC = 0.18033688011112042f;   // log2(e)/8

    for (int kt = 0; kt <= qt; kt++) {
        CP_WAIT1();
        __syncthreads();
        const uint32_t kv = sb + (kt & 1) * KV_STG;

        float s[8][4];
#pragma unroll
        for (int nt = 0; nt < 8; nt++)
#pragma unroll
            for (int r = 0; r < 4; r++) s[nt][r] = 0.f;
#pragma unroll
        for (int ks = 0; ks < 4; ks++) {
            uint32_t qh[4], ql[4];
            ldmA(qh, sb + S_QHI + a_row_off + ks * 32);
            ldmA(ql, sb + S_QLO + a_row_off + ks * 32);
#pragma unroll
            for (int nt = 0; nt < 8; nt++) {
                uint32_t kh[2], kl[2];
                const uint32_t bo = b_row_off + nt * 8 * ROWB + ks * 32;
                ldmB(kh, kv + S_KHI + bo);
                ldmB(kl, kv + S_KLO + bo);
                mma_bf16(s[nt], qh, kh);
                mma_bf16(s[nt], qh, kl);
                mma_bf16(s[nt], ql, kh);
            }
        }
#pragma unroll
        for (int nt = 0; nt < 8; nt++)
#pragma unroll
            for (int r = 0; r < 4; r++) s[nt][r] *= SC;

        if (kt == qt) {
#pragma unroll
            for (int nt = 0; nt < 8; nt++) {
                const int c = nt * 8 + colx;
                if (c     > row_lo)     s[nt][0] = -1e30f;
                if (c + 1 > row_lo)     s[nt][1] = -1e30f;
                if (c     > row_lo + 8) s[nt][2] = -1e30f;
                if (c + 1 > row_lo + 8) s[nt][3] = -1e30f;
            }
        }

        float r0 = -1e30f, r1 = -1e30f;
#pragma unroll
        for (int nt = 0; nt < 8; nt++) {
            r0 = fmaxf(r0, fmaxf(s[nt][0], s[nt][1]));
            r1 = fmaxf(r1, fmaxf(s[nt][2], s[nt][3]));
        }
        r0 = fmaxf(r0, __shfl_xor_sync(0xffffffffu, r0, 1));
        r0 = fmaxf(r0, __shfl_xor_sync(0xffffffffu, r0, 2));
        r1 = fmaxf(r1, __shfl_xor_sync(0xffffffffu, r1, 1));
        r1 = fmaxf(r1, __shfl_xor_sync(0xffffffffu, r1, 2));
        const float mn0 = fmaxf(mi0, r0), mn1 = fmaxf(mi1, r1);
        const float c0 = ex2f(mi0 - mn0), c1 = ex2f(mi1 - mn1);
        float sum0 = 0.f, sum1 = 0.f;
#pragma unroll
        for (int nt = 0; nt < 8; nt++) {
            s[nt][0] = ex2f(s[nt][0] - mn0);
            s[nt][1] = ex2f(s[nt][1] - mn0);
            s[nt][2] = ex2f(s[nt][2] - mn1);
            s[nt][3] = ex2f(s[nt][3] - mn1);
            sum0 += s[nt][0] + s[nt][1];
            sum1 += s[nt][2] + s[nt][3];
        }
        sum0 += __shfl_xor_sync(0xffffffffu, sum0, 1);
        sum0 += __shfl_xor_sync(0xffffffffu, sum0, 2);
        sum1 += __shfl_xor_sync(0xffffffffu, sum1, 1);
        sum1 += __shfl_xor_sync(0xffffffffu, sum1, 2);
        li0 = li0 * c0 + sum0; li1 = li1 * c1 + sum1;
        mi0 = mn0; mi1 = mn1;
#pragma unroll
        for (int d = 0; d < 8; d++) {
            o[d][0] *= c0; o[d][1] *= c0; o[d][2] *= c1; o[d][3] *= c1;
        }

        uint32_t ahi[4][4], alo[4][4];
#pragma unroll
        for (int kvs = 0; kvs < 4; kvs++) {
            const float* p0 = s[2 * kvs];
            const float* p1 = s[2 * kvs + 1];
            ahi[kvs][0] = pack2(p0[0], p0[1]);
            ahi[kvs][1] = pack2(p0[2], p0[3]);
            ahi[kvs][2] = pack2(p1[0], p1[1]);
            ahi[kvs][3] = pack2(p1[2], p1[3]);
#pragma unroll
            for (int q = 0; q < 4; q++) {
                const float* pp = (q < 2) ? p0 : p1;
                const int base = (q & 1) * 2;
                const uint32_t hreg = ahi[kvs][q];
                float f0 = __uint_as_float(hreg << 16);
                float f1 = __uint_as_float(hreg & 0xffff0000u);
                alo[kvs][q] = pack2(pp[base] - f0, pp[base + 1] - f1);
            }
        }

#pragma unroll
        for (int kvs = 0; kvs < 4; kvs++) {
#pragma unroll
            for (int d = 0; d < 8; d++) {
                uint32_t vh[2], vl[2];
                const uint32_t vo = (16 * kvs) * ROWB + v_row_off + d * 16;
                ldmVT(vh, kv + S_VHI + vo);
                ldmVT(vl, kv + S_VLO + vo);
                mma_bf16(o[d], ahi[kvs], vh);
                mma_bf16(o[d], alo[kvs], vh);
                mma_bf16(o[d], ahi[kvs], vl);
            }
        }

        __syncthreads();
        if (kt + 2 <= qt) load_kv(kt & 1, kt + 2);
        CP_COMMIT();
    }

    const float inv0 = 1.f / li0, inv1 = 1.f / li1;
    const int grow0 = q0 + row_lo;
#pragma unroll
    for (int d = 0; d < 8; d++) {
        const int col = h * 64 + d * 8 + colx;
        size_t i0 = ((size_t)b * S_ + grow0) * D_ + col;
        size_t i1 = ((size_t)b * S_ + grow0 + 8) * D_ + col;
        *(float2*)(g_AOt + i0) =
            make_float2(tf32r(o[d][0] * inv0), tf32r(o[d][1] * inv0));
        *(float2*)(g_AOt + i1) =
            make_float2(tf32r(o[d][2] * inv1), tf32r(o[d][3] * inv1));
    }
}

// ---------------------------------------------------------------------------
// Host
// ---------------------------------------------------------------------------
extern "C" void kernel_launch(void* const* d_in, const int* in_sizes, int n_in,
                              void* d_out, int out_size)
{
    const float* x  = (const float*)d_in[0];
    const float* qw = (const float*)d_in[1];
    const float* kw = (const float*)d_in[2];
    const float* vw = (const float*)d_in[3];
    const float* ow = (const float*)d_in[4];
    const int*   tp = (const int*)d_in[6];
    float* out = (float*)d_out;

    void *xhi, *xlo, *xt, *whi, *wlo, *wt, *aot;
    cudaGetSymbolAddress(&xhi, g_Xhi);
    cudaGetSymbolAddress(&xlo, g_Xlo);
    cudaGetSymbolAddress(&xt,  g_Xt);
    cudaGetSymbolAddress(&whi, g_Whi);
    cudaGetSymbolAddress(&wlo, g_Wlo);
    cudaGetSymbolAddress(&wt,  g_Wt);
    cudaGetSymbolAddress(&aot, g_AOt);

    __nv_bfloat16* Xhi = (__nv_bfloat16*)xhi;
    __nv_bfloat16* Xlo = (__nv_bfloat16*)xlo;
    float*         Xt  = (float*)xt;
    __nv_bfloat16* Whi = (__nv_bfloat16*)whi;
    __nv_bfloat16* Wlo = (__nv_bfloat16*)wlo;
    float*         Wt  = (float*)wt;
    float*         AOt = (float*)aot;

    prep_x<<<M_*D_/4/256, 256>>>(x, Xhi, Xlo, Xt, M_*D_);
    split_bf16<<<D_*D_/4/256, 256>>>(qw, Whi, Wlo, D_*D_);
    split_bf16<<<D_*D_/4/256, 256>>>(kw, Whi + (size_t)D_*D_, Wlo + (size_t)D_*D_, D_*D_);
    conv_tf32<<<D_*D_/4/256, 256>>>(vw, Wt, D_*D_);
    conv_tf32<<<D_*D_/4/256, 256>>>(ow, Wt + (size_t)D_*D_, D_*D_);

    cudaFuncSetAttribute(gemm_mma<1>, cudaFuncAttributeMaxDynamicSharedMemorySize, GEMM_SMEM);
    cudaFuncSetAttribute(gemm_mma<2>, cudaFuncAttributeMaxDynamicSharedMemorySize, GEMM_SMEM);
    cudaFuncSetAttribute(gemm_tf32<0>, cudaFuncAttributeMaxDynamicSharedMemorySize, TSMEM);
    cudaFuncSetAttribute(gemm_tf32<3>, cudaFuncAttributeMaxDynamicSharedMemorySize, TSMEM);

    dim3 ggrid(M_ / BM, D_ / BN);   // (32, 16)
    gemm_mma<1><<<ggrid, 256, GEMM_SMEM>>>(Xhi, Xlo, Whi, Wlo, tp);
    gemm_mma<2><<<ggrid, 256, GEMM_SMEM>>>(Xhi, Xlo,
        Whi + (size_t)D_*D_, Wlo + (size_t)D_*D_, tp);
    gemm_tf32<3><<<ggrid, 256, TSMEM>>>(Xt, Wt, nullptr);

    cudaFuncSetAttribute(attn_mma, cudaFuncAttributeMaxDynamicSharedMemorySize, ATT_SMEM);
    dim3 agrid(S_ / 64, H_, B_);    // (32, 16, 2)
    attn_mma<<<agrid, 128, ATT_SMEM>>>();

    gemm_tf32<0><<<ggrid, 256, TSMEM>>>(AOt, Wt + (size_t)D_*D_, out);
}

// round 6
// speedup vs baseline: 2.8454x; 1.0900x over previous
#include <cuda_runtime.h>
#include <cuda_bf16.h>
#include <math.h>
#include <stdint.h>

#define B_  2
#define S_  2048
#define D_  1024
#define H_  16
#define DK_ 64
#define M_  (B_*S_)

// ---------------------------------------------------------------------------
// Scratch (__device__ globals; allocation-free contract)
// ---------------------------------------------------------------------------
__device__ __align__(16) __nv_bfloat16 g_Xhi[M_*D_];
__device__ __align__(16) __nv_bfloat16 g_Xlo[M_*D_];
__device__ __align__(16) float         g_Xt [M_*D_];
__device__ __align__(16) __nv_bfloat16 g_Whi[2*(size_t)D_*D_];  // q,k weights
__device__ __align__(16) __nv_bfloat16 g_Wlo[2*(size_t)D_*D_];
__device__ __align__(16) float         g_Wt [2*(size_t)D_*D_];  // v,o weights
__device__ __align__(16) float         g_AOt[M_*D_];
__device__ __align__(16) float         g_Q[B_*H_*S_*DK_];       // [B,H,S,DK] tf32, pre-scaled
__device__ __align__(16) float         g_K[B_*H_*S_*DK_];       // [B,H,S,DK] tf32
__device__ __align__(16) float         g_V[B_*H_*S_*DK_];       // [B,H,DK,S] tf32 (transposed!)

// ---------------------------------------------------------------------------
// PTX wrappers (arch-neutral sm_80-class)
// ---------------------------------------------------------------------------
__device__ __forceinline__ uint32_t smem_u32(const void* p) {
    uint32_t a;
    asm("{ .reg .u64 t; cvta.to.shared.u64 t, %1; cvt.u32.u64 %0, t; }"
        : "=r"(a) : "l"(p));
    return a;
}
__device__ __forceinline__ void cp16(uint32_t dst, const void* src) {
    asm volatile("cp.async.cg.shared.global [%0], [%1], 16;"
                 :: "r"(dst), "l"(src));
}
#define CP_COMMIT() asm volatile("cp.async.commit_group;")
#define CP_WAIT1()  asm volatile("cp.async.wait_group 1;")

__device__ __forceinline__ void ldmA(uint32_t (&a)[4], uint32_t addr) {
    asm volatile("ldmatrix.sync.aligned.m8n8.x4.shared.b16 {%0,%1,%2,%3}, [%4];"
                 : "=r"(a[0]), "=r"(a[1]), "=r"(a[2]), "=r"(a[3]) : "r"(addr));
}
__device__ __forceinline__ void ldmB(uint32_t (&b)[2], uint32_t addr) {
    asm volatile("ldmatrix.sync.aligned.m8n8.x2.shared.b16 {%0,%1}, [%2];"
                 : "=r"(b[0]), "=r"(b[1]) : "r"(addr));
}
__device__ __forceinline__ void mma_bf16(float (&d)[4], const uint32_t (&a)[4],
                                         const uint32_t (&b)[2]) {
    asm volatile(
        "mma.sync.aligned.m16n8k16.row.col.f32.bf16.bf16.f32 "
        "{%0,%1,%2,%3}, {%4,%5,%6,%7}, {%8,%9}, {%0,%1,%2,%3};"
        : "+f"(d[0]), "+f"(d[1]), "+f"(d[2]), "+f"(d[3])
        : "r"(a[0]), "r"(a[1]), "r"(a[2]), "r"(a[3]), "r"(b[0]), "r"(b[1]));
}
__device__ __forceinline__ void mma_tf32(float (&d)[4], const uint32_t (&a)[4],
                                         uint32_t b0, uint32_t b1) {
    asm volatile(
        "mma.sync.aligned.m16n8k8.row.col.f32.tf32.tf32.f32 "
        "{%0,%1,%2,%3}, {%4,%5,%6,%7}, {%8,%9}, {%0,%1,%2,%3};"
        : "+f"(d[0]), "+f"(d[1]), "+f"(d[2]), "+f"(d[3])
        : "r"(a[0]), "r"(a[1]), "r"(a[2]), "r"(a[3]), "r"(b0), "r"(b1));
}
__device__ __forceinline__ uint32_t pack2(float a, float b) {
    uint32_t r;
    asm("cvt.rn.bf16x2.f32 %0, %1, %2;" : "=r"(r) : "f"(b), "f"(a));
    return r;
}
__device__ __forceinline__ float ex2f(float x) {
    float y; asm("ex2.approx.f32 %0, %1;" : "=f"(y) : "f"(x)); return y;
}
__device__ __forceinline__ float tf32r(float x) {
    uint32_t r; asm("cvt.rna.tf32.f32 %0, %1;" : "=r"(r) : "f"(x));
    return __uint_as_float(r);
}
__device__ __forceinline__ void store_hilo(__nv_bfloat16* H, __nv_bfloat16* L,
                                           size_t idx, float v0, float v1) {
    uint32_t hi = pack2(v0, v1);
    float fh0 = __uint_as_float(hi << 16);
    float fh1 = __uint_as_float(hi & 0xffff0000u);
    uint32_t lo = pack2(v0 - fh0, v1 - fh1);
    *(uint32_t*)(H + idx) = hi;
    *(uint32_t*)(L + idx) = lo;
}

#define SC_Q 0.18033688011112042f   // log2(e)/8, folded into Q

// ---------------------------------------------------------------------------
// Prep kernels
// ---------------------------------------------------------------------------
__global__ __launch_bounds__(256)
void prep_x(const float* __restrict__ src, __nv_bfloat16* __restrict__ hi,
            __nv_bfloat16* __restrict__ lo, float* __restrict__ t, int n)
{
    int i = (blockIdx.x * blockDim.x + threadIdx.x) * 4;
    if (i >= n) return;
    float4 v = *(const float4*)(src + i);
    store_hilo(hi, lo, i,     v.x, v.y);
    store_hilo(hi, lo, i + 2, v.z, v.w);
    *(float4*)(t + i) = make_float4(tf32r(v.x), tf32r(v.y), tf32r(v.z), tf32r(v.w));
}
__global__ __launch_bounds__(256)
void split_bf16(const float* __restrict__ src, __nv_bfloat16* __restrict__ hi,
                __nv_bfloat16* __restrict__ lo, int n)
{
    int i = (blockIdx.x * blockDim.x + threadIdx.x) * 4;
    if (i >= n) return;
    float4 v = *(const float4*)(src + i);
    store_hilo(hi, lo, i,     v.x, v.y);
    store_hilo(hi, lo, i + 2, v.z, v.w);
}
__global__ __launch_bounds__(256)
void conv_tf32(const float* __restrict__ src, float* __restrict__ dst, int n)
{
    int i = (blockIdx.x * blockDim.x + threadIdx.x) * 4;
    if (i >= n) return;
    float4 v = *(const float4*)(src + i);
    *(float4*)(dst + i) = make_float4(tf32r(v.x), tf32r(v.y), tf32r(v.z), tf32r(v.w));
}

// ---------------------------------------------------------------------------
// Split-bf16 GEMM (3-pass HMMA). DEST: 1 = Q (+RoPE, *SC_Q), 2 = K (+RoPE).
// Writes fp32 tf32-rounded [B,H,S,DK].
// ---------------------------------------------------------------------------
#define BM 128
#define BN 64
#define BK 32
#define SA_HI 0
#define SA_LO (BM*80)
#define SB_HI (2*BM*80)
#define SB_LO (2*BM*80 + BN*80)
#define STG_BYTES (2*BM*80 + 2*BN*80)
#define GEMM_SMEM (3*STG_BYTES)
#define NIT (D_/BK)

template<int DEST>
__global__ __launch_bounds__(256)
void gemm_mma(const __nv_bfloat16* __restrict__ Ahi,
              const __nv_bfloat16* __restrict__ Alo,
              const __nv_bfloat16* __restrict__ Bhi,
              const __nv_bfloat16* __restrict__ Blo,
              const int* __restrict__ tokpos)
{
    extern __shared__ __align__(16) char smem[];
    const uint32_t sb = smem_u32(smem);
    const int tid  = threadIdx.x;
    const int lane = tid & 31, w = tid >> 5;
    const int wm = (w & 3) * 32;
    const int wn = (w >> 2) * 32;
    const int m0 = blockIdx.x * BM;
    const int n0 = blockIdx.y * BN;

    const int arow0 = tid >> 2, acc4 = (tid & 3);
    const int arow1 = (tid + 256) >> 2;
    const int brow  = tid >> 2;

    auto load_stage = [&](int st, int it) {
        const uint32_t s = sb + st * STG_BYTES;
        const int kk = it * BK;
        const size_t ga0 = (size_t)(m0 + arow0) * D_ + kk + acc4 * 8;
        const size_t ga1 = (size_t)(m0 + arow1) * D_ + kk + acc4 * 8;
        const uint32_t so0 = arow0 * 80 + acc4 * 16;
        const uint32_t so1 = arow1 * 80 + acc4 * 16;
        cp16(s + SA_HI + so0, Ahi + ga0);
        cp16(s + SA_HI + so1, Ahi + ga1);
        cp16(s + SA_LO + so0, Alo + ga0);
        cp16(s + SA_LO + so1, Alo + ga1);
        const size_t gb = (size_t)(n0 + brow) * D_ + kk + acc4 * 8;
        const uint32_t sob = brow * 80 + acc4 * 16;
        cp16(s + SB_HI + sob, Bhi + gb);
        cp16(s + SB_LO + sob, Blo + gb);
    };

    float acc[2][4][4];
#pragma unroll
    for (int mt = 0; mt < 2; mt++)
#pragma unroll
        for (int nt = 0; nt < 4; nt++)
#pragma unroll
            for (int r = 0; r < 4; r++) acc[mt][nt][r] = 0.f;

    load_stage(0, 0); CP_COMMIT();
    load_stage(1, 1); CP_COMMIT();

    const uint32_t a_row_off = (wm + (lane & 15)) * 80 + ((lane >> 4) << 4);
    const uint32_t b_row_off = (wn + (lane & 7)) * 80 + (((lane >> 3) & 1) << 4);

    for (int it = 0; it < NIT; it++) {
        CP_WAIT1();
        __syncthreads();
        if (it + 2 < NIT) load_stage((it + 2) % 3, it + 2);
        CP_COMMIT();

        const uint32_t s = sb + (it % 3) * STG_BYTES;
#pragma unroll
        for (int ks = 0; ks < 2; ks++) {
            const uint32_t kofs = ks * 32;
            uint32_t a_hi[2][4], a_lo[2][4], b_hi[4][2], b_lo[4][2];
#pragma unroll
            for (int mt = 0; mt < 2; mt++) {
                const uint32_t ao = a_row_off + mt * 16 * 80 + kofs;
                ldmA(a_hi[mt], s + SA_HI + ao);
                ldmA(a_lo[mt], s + SA_LO + ao);
            }
#pragma unroll
            for (int nt = 0; nt < 4; nt++) {
                const uint32_t bo = b_row_off + nt * 8 * 80 + kofs;
                ldmB(b_hi[nt], s + SB_HI + bo);
                ldmB(b_lo[nt], s + SB_LO + bo);
            }
#pragma unroll
            for (int mt = 0; mt < 2; mt++)
#pragma unroll
                for (int nt = 0; nt < 4; nt++) {
                    mma_bf16(acc[mt][nt], a_hi[mt], b_hi[nt]);
                    mma_bf16(acc[mt][nt], a_hi[mt], b_lo[nt]);
                    mma_bf16(acc[mt][nt], a_lo[mt], b_hi[nt]);
                }
        }
    }

#pragma unroll
    for (int mt = 0; mt < 2; mt++) {
        const int r0 = m0 + wm + mt * 16 + (lane >> 2);
#pragma unroll
        for (int nt = 0; nt < 4; nt++) {
            const int ncol = n0 + wn + nt * 8 + (lane & 3) * 2;
            float* Dst = (DEST == 1) ? g_Q : g_K;
            const int h = ncol >> 6, dk = ncol & 63;
            const float fr = powf(10000.f, -(float)dk / 64.f);
#pragma unroll
            for (int rr = 0; rr < 2; rr++) {
                const int m = r0 + rr * 8;
                const int bb = m >> 11, ss = m & (S_ - 1);
                const float pos = (float)tokpos[ss];
                float sn, cs;
                sincosf(pos * fr, &sn, &cs);
                float e  = acc[mt][nt][2 * rr];
                float od = acc[mt][nt][2 * rr + 1];
                float v0 = e * cs - od * sn;
                float v1 = e * sn + od * cs;
                if (DEST == 1) { v0 *= SC_Q; v1 *= SC_Q; }
                size_t idx = (((size_t)(bb * H_ + h)) * S_ + ss) * DK_ + dk;
                *(float2*)(Dst + idx) = make_float2(tf32r(v0), tf32r(v1));
            }
        }
    }
}

// ---------------------------------------------------------------------------
// Single-pass tf32 GEMM. DEST: 0 = fp32 out [M,D]; 3 = V transposed [B,H,DK,S].
// ---------------------------------------------------------------------------
#define TROW 36
#define TSB_OFF (BM*TROW)
#define TSTG ((BM*TROW + BN*TROW)*4)
#define TSMEM (3*TSTG)

template<int DEST>
__global__ __launch_bounds__(256)
void gemm_tf32(const float* __restrict__ A, const float* __restrict__ W,
               float* __restrict__ Cout)
{
    extern __shared__ __align__(16) char smem[];
    const int tid  = threadIdx.x;
    const int lane = tid & 31, w = tid >> 5;
    const int wm = (w & 3) * 32;
    const int wn = (w >> 2) * 32;
    const int m0 = blockIdx.x * BM;
    const int n0 = blockIdx.y * BN;
    const int rg = lane >> 2, tc = lane & 3;

    auto load_stage = [&](int st, int it) {
        float* s = (float*)(smem + st * TSTG);
        const int kk = it * BK;
#pragma unroll
        for (int i = 0; i < 4; i++) {
            int idx = tid + i * 256;
            int row = idx >> 3, ch = idx & 7;
            cp16(smem_u32(s + row * TROW + ch * 4),
                 A + (size_t)(m0 + row) * D_ + kk + ch * 4);
        }
        float* sB = s + TSB_OFF;
#pragma unroll
        for (int i = 0; i < 2; i++) {
            int idx = tid + i * 256;
            int row = idx >> 3, ch = idx & 7;
            cp16(smem_u32(sB + row * TROW + ch * 4),
                 W + (size_t)(n0 + row) * D_ + kk + ch * 4);
        }
    };

    float acc[2][4][4];
#pragma unroll
    for (int mt = 0; mt < 2; mt++)
#pragma unroll
        for (int nt = 0; nt < 4; nt++)
#pragma unroll
            for (int r = 0; r < 4; r++) acc[mt][nt][r] = 0.f;

    load_stage(0, 0); CP_COMMIT();
    load_stage(1, 1); CP_COMMIT();

    for (int it = 0; it < NIT; it++) {
        CP_WAIT1();
        __syncthreads();
        if (it + 2 < NIT) load_stage((it + 2) % 3, it + 2);
        CP_COMMIT();

        const uint32_t* s  = (const uint32_t*)(smem + (it % 3) * TSTG);
        const uint32_t* sB = s + TSB_OFF;
#pragma unroll
        for (int ks = 0; ks < 4; ks++) {
            uint32_t a[2][4];
#pragma unroll
            for (int mt = 0; mt < 2; mt++) {
                const uint32_t* base = s + (wm + mt * 16 + rg) * TROW + ks * 8 + tc;
                a[mt][0] = base[0];
                a[mt][1] = base[8 * TROW];
                a[mt][2] = base[4];
                a[mt][3] = base[8 * TROW + 4];
            }
#pragma unroll
            for (int nt = 0; nt < 4; nt++) {
                const uint32_t* bp = sB + (wn + nt * 8 + rg) * TROW + ks * 8 + tc;
                const uint32_t b0 = bp[0], b1 = bp[4];
#pragma unroll
                for (int mt = 0; mt < 2; mt++)
                    mma_tf32(acc[mt][nt], a[mt], b0, b1);
            }
        }
    }

#pragma unroll
    for (int mt = 0; mt < 2; mt++) {
        const int r0 = m0 + wm + mt * 16 + (lane >> 2);
#pragma unroll
        for (int nt = 0; nt < 4; nt++) {
            const int ncol = n0 + wn + nt * 8 + (lane & 3) * 2;
            if (DEST == 0) {
                *(float2*)(Cout + (size_t)r0 * D_ + ncol) =
                    make_float2(acc[mt][nt][0], acc[mt][nt][1]);
                *(float2*)(Cout + (size_t)(r0 + 8) * D_ + ncol) =
                    make_float2(acc[mt][nt][2], acc[mt][nt][3]);
            } else {
                const int h = ncol >> 6, dk = ncol & 63;
#pragma unroll
                for (int rr = 0; rr < 2; rr++) {
                    const int m = r0 + rr * 8;
                    const int bb = m >> 11, ss = m & (S_ - 1);
                    size_t base = ((size_t)(bb * H_ + h)) * DK_ * S_;
                    g_V[base + (size_t)dk * S_ + ss]       = tf32r(acc[mt][nt][2 * rr]);
                    g_V[base + (size_t)(dk + 1) * S_ + ss] = tf32r(acc[mt][nt][2 * rr + 1]);
                }
            }
        }
    }
}

// ---------------------------------------------------------------------------
// Flash attention, single-pass tf32 (QK^T and PV). CTA = 64q x 64kv, 4 warps.
// Q pre-scaled by log2(e)/8 at projection time. V pre-transposed [d][s].
// ---------------------------------------------------------------------------
#define AST 68                               // smem row stride in floats
#define OKV0 (64*AST)                        // K0; stage block = 2*64*AST
#define OP   (64*AST + 2*2*64*AST)           // per-warp P regions
#define ATT_FLOATS (OP + 4*16*AST)           // 26112
#define ATT_SMEM (ATT_FLOATS*4)              // 104448

__global__ __launch_bounds__(128)
void attn_tf32()
{
    extern __shared__ __align__(16) float sm[];
    uint32_t* smw = (uint32_t*)sm;
    const int tid = threadIdx.x;
    const int lane = tid & 31, w = tid >> 5;
    const int rg = lane >> 2, tc = lane & 3;
    const int qt = (int)(gridDim.x - 1 - blockIdx.x);
    const int h  = blockIdx.y, b = blockIdx.z;
    const int q0 = qt * 64;
    const size_t gqk = ((size_t)(b * H_ + h)) * S_ * DK_;   // Q,K base
    const size_t gvt = ((size_t)(b * H_ + h)) * DK_ * S_;   // V^T base

    // Q tile load
#pragma unroll
    for (int i = 0; i < 8; i++) {
        int idx = tid + i * 128;
        int r = idx >> 4, ch = idx & 15;
        cp16(smem_u32(sm + r * AST + ch * 4),
             g_Q + gqk + (size_t)(q0 + r) * DK_ + ch * 4);
    }
    auto load_kv = [&](int st, int kt) {
        float* sK = sm + OKV0 + st * (2 * 64 * AST);
        float* sV = sK + 64 * AST;
#pragma unroll
        for (int i = 0; i < 8; i++) {
            int idx = tid + i * 128;
            int r = idx >> 4, ch = idx & 15;
            cp16(smem_u32(sK + r * AST + ch * 4),
                 g_K + gqk + (size_t)(kt * 64 + r) * DK_ + ch * 4);
            cp16(smem_u32(sV + r * AST + ch * 4),
                 g_V + gvt + (size_t)r * S_ + kt * 64 + ch * 4);
        }
    };
    load_kv(0, 0); CP_COMMIT();
    if (qt >= 1) load_kv(1, 1);
    CP_COMMIT();

    CP_WAIT1();
    __syncthreads();

    // preload Q fragments (stay fixed across kv tiles)
    uint32_t qf[8][4];
    {
        const uint32_t* q = smw + (w * 16 + rg) * AST;
#pragma unroll
        for (int ks = 0; ks < 8; ks++) {
            qf[ks][0] = q[ks * 8 + tc];
            qf[ks][1] = q[8 * AST + ks * 8 + tc];
            qf[ks][2] = q[ks * 8 + tc + 4];
            qf[ks][3] = q[8 * AST + ks * 8 + tc + 4];
        }
    }

    float o[8][4];
#pragma unroll
    for (int d = 0; d < 8; d++)
#pragma unroll
        for (int r = 0; r < 4; r++) o[d][r] = 0.f;
    float mi0 = -1e30f, mi1 = -1e30f, li0 = 0.f, li1 = 0.f;
    const int row_lo = w * 16 + rg;
    const int colx   = 2 * tc;
    float*    pwf = sm  + OP + w * 16 * AST;
    uint32_t* pww = smw + OP + w * 16 * AST;

    for (int kt = 0; kt <= qt; kt++) {
        if (kt) { CP_WAIT1(); __syncthreads(); }
        const uint32_t* sK = smw + OKV0 + (kt & 1) * (2 * 64 * AST);
        const uint32_t* sV = sK + 64 * AST;

        // ---- S = Q K^T (tf32 single pass) ----
        float s[8][4];
#pragma unroll
        for (int nt = 0; nt < 8; nt++)
#pragma unroll
            for (int r = 0; r < 4; r++) s[nt][r] = 0.f;
#pragma unroll
        for (int ks = 0; ks < 8; ks++)
#pragma unroll
            for (int nt = 0; nt < 8; nt++) {
                const uint32_t* kp = sK + (nt * 8 + rg) * AST + ks * 8 + tc;
                mma_tf32(s[nt], qf[ks], kp[0], kp[4]);
            }

        if (kt == qt) {   // causal mask on diagonal tile
#pragma unroll
            for (int nt = 0; nt < 8; nt++) {
                const int c = nt * 8 + colx;
                if (c     > row_lo)     s[nt][0] = -1e30f;
                if (c + 1 > row_lo)     s[nt][1] = -1e30f;
                if (c     > row_lo + 8) s[nt][2] = -1e30f;
                if (c + 1 > row_lo + 8) s[nt][3] = -1e30f;
            }
        }

        // ---- online softmax (base-2; scale folded into Q) ----
        float r0 = -1e30f, r1 = -1e30f;
#pragma unroll
        for (int nt = 0; nt < 8; nt++) {
            r0 = fmaxf(r0, fmaxf(s[nt][0], s[nt][1]));
            r1 = fmaxf(r1, fmaxf(s[nt][2], s[nt][3]));
        }
        r0 = fmaxf(r0, __shfl_xor_sync(0xffffffffu, r0, 1));
        r0 = fmaxf(r0, __shfl_xor_sync(0xffffffffu, r0, 2));
        r1 = fmaxf(r1, __shfl_xor_sync(0xffffffffu, r1, 1));
        r1 = fmaxf(r1, __shfl_xor_sync(0xffffffffu, r1, 2));
        const float mn0 = fmaxf(mi0, r0), mn1 = fmaxf(mi1, r1);
        const float c0 = ex2f(mi0 - mn0), c1 = ex2f(mi1 - mn1);
        float sum0 = 0.f, sum1 = 0.f;
#pragma unroll
        for (int nt = 0; nt < 8; nt++) {
            s[nt][0] = ex2f(s[nt][0] - mn0);
            s[nt][1] = ex2f(s[nt][1] - mn0);
            s[nt][2] = ex2f(s[nt][2] - mn1);
            s[nt][3] = ex2f(s[nt][3] - mn1);
            sum0 += s[nt][0] + s[nt][1];
            sum1 += s[nt][2] + s[nt][3];
        }
        sum0 += __shfl_xor_sync(0xffffffffu, sum0, 1);
        sum0 += __shfl_xor_sync(0xffffffffu, sum0, 2);
        sum1 += __shfl_xor_sync(0xffffffffu, sum1, 1);
        sum1 += __shfl_xor_sync(0xffffffffu, sum1, 2);
        li0 = li0 * c0 + sum0; li1 = li1 * c1 + sum1;
        mi0 = mn0; mi1 = mn1;
#pragma unroll
        for (int d = 0; d < 8; d++) {
            o[d][0] *= c0; o[d][1] *= c0; o[d][2] *= c1; o[d][3] *= c1;
        }

        // ---- stage P (tf32-rounded) in per-warp smem ----
#pragma unroll
        for (int nt = 0; nt < 8; nt++) {
            *(float2*)(pwf + rg * AST + nt * 8 + colx) =
                make_float2(tf32r(s[nt][0]), tf32r(s[nt][1]));
            *(float2*)(pwf + (rg + 8) * AST + nt * 8 + colx) =
                make_float2(tf32r(s[nt][2]), tf32r(s[nt][3]));
        }
        __syncwarp();

        // ---- O += P V (tf32 single pass) ----
#pragma unroll
        for (int ks = 0; ks < 8; ks++) {
            uint32_t a[4];
            const uint32_t* pb = pww + rg * AST + ks * 8 + tc;
            a[0] = pb[0];
            a[1] = pb[8 * AST];
            a[2] = pb[4];
            a[3] = pb[8 * AST + 4];
#pragma unroll
            for (int nt = 0; nt < 8; nt++) {
                const uint32_t* vp = sV + (nt * 8 + rg) * AST + ks * 8 + tc;
                mma_tf32(o[nt], a, vp[0], vp[4]);
            }
        }

        __syncthreads();
        if (kt + 2 <= qt) load_kv(kt & 1, kt + 2);
        CP_COMMIT();
    }

    // ---- epilogue: normalize, write tf32 fp32 [B,S,H*DK] ----
    const float inv0 = 1.f / li0, inv1 = 1.f / li1;
    const int grow0 = q0 + row_lo;
#pragma unroll
    for (int d = 0; d < 8; d++) {
        const int col = h * 64 + d * 8 + colx;
        size_t i0 = ((size_t)b * S_ + grow0) * D_ + col;
        size_t i1 = ((size_t)b * S_ + grow0 + 8) * D_ + col;
        *(float2*)(g_AOt + i0) =
            make_float2(tf32r(o[d][0] * inv0), tf32r(o[d][1] * inv0));
        *(float2*)(g_AOt + i1) =
            make_float2(tf32r(o[d][2] * inv1), tf32r(o[d][3] * inv1));
    }
}

// ---------------------------------------------------------------------------
// Host
// ---------------------------------------------------------------------------
extern "C" void kernel_launch(void* const* d_in, const int* in_sizes, int n_in,
                              void* d_out, int out_size)
{
    const float* x  = (const float*)d_in[0];
    const float* qw = (const float*)d_in[1];
    const float* kw = (const float*)d_in[2];
    const float* vw = (const float*)d_in[3];
    const float* ow = (const float*)d_in[4];
    const int*   tp = (const int*)d_in[6];
    float* out = (float*)d_out;

    void *xhi, *xlo, *xt, *whi, *wlo, *wt, *aot;
    cudaGetSymbolAddress(&xhi, g_Xhi);
    cudaGetSymbolAddress(&xlo, g_Xlo);
    cudaGetSymbolAddress(&xt,  g_Xt);
    cudaGetSymbolAddress(&whi, g_Whi);
    cudaGetSymbolAddress(&wlo, g_Wlo);
    cudaGetSymbolAddress(&wt,  g_Wt);
    cudaGetSymbolAddress(&aot, g_AOt);

    __nv_bfloat16* Xhi = (__nv_bfloat16*)xhi;
    __nv_bfloat16* Xlo = (__nv_bfloat16*)xlo;
    float*         Xt  = (float*)xt;
    __nv_bfloat16* Whi = (__nv_bfloat16*)whi;
    __nv_bfloat16* Wlo = (__nv_bfloat16*)wlo;
    float*         Wt  = (float*)wt;
    float*         AOt = (float*)aot;

    prep_x<<<M_*D_/4/256, 256>>>(x, Xhi, Xlo, Xt, M_*D_);
    split_bf16<<<D_*D_/4/256, 256>>>(qw, Whi, Wlo, D_*D_);
    split_bf16<<<D_*D_/4/256, 256>>>(kw, Whi + (size_t)D_*D_, Wlo + (size_t)D_*D_, D_*D_);
    conv_tf32<<<D_*D_/4/256, 256>>>(vw, Wt, D_*D_);
    conv_tf32<<<D_*D_/4/256, 256>>>(ow, Wt + (size_t)D_*D_, D_*D_);

    cudaFuncSetAttribute(gemm_mma<1>, cudaFuncAttributeMaxDynamicSharedMemorySize, GEMM_SMEM);
    cudaFuncSetAttribute(gemm_mma<2>, cudaFuncAttributeMaxDynamicSharedMemorySize, GEMM_SMEM);
    cudaFuncSetAttribute(gemm_tf32<0>, cudaFuncAttributeMaxDynamicSharedMemorySize, TSMEM);
    cudaFuncSetAttribute(gemm_tf32<3>, cudaFuncAttributeMaxDynamicSharedMemorySize, TSMEM);
    cudaFuncSetAttribute(attn_tf32, cudaFuncAttributeMaxDynamicSharedMemorySize, ATT_SMEM);

    dim3 ggrid(M_ / BM, D_ / BN);   // (32, 16)
    gemm_mma<1><<<ggrid, 256, GEMM_SMEM>>>(Xhi, Xlo, Whi, Wlo, tp);
    gemm_mma<2><<<ggrid, 256, GEMM_SMEM>>>(Xhi, Xlo,
        Whi + (size_t)D_*D_, Wlo + (size_t)D_*D_, tp);
    gemm_tf32<3><<<ggrid, 256, TSMEM>>>(Xt, Wt, nullptr);

    dim3 agrid(S_ / 64, H_, B_);    // (32, 16, 2)
    attn_tf32<<<agrid, 128, ATT_SMEM>>>();

    gemm_tf32<0><<<ggrid, 256, TSMEM>>>(AOt, Wt + (size_t)D_*D_, out);
}

// round 7
// speedup vs baseline: 3.1127x; 1.0939x over previous
#include <cuda_runtime.h>
#include <math.h>
#include <stdint.h>

#define B_  2
#define S_  2048
#define D_  1024
#define H_  16
#define DK_ 64
#define M_  (B_*S_)

// ---------------------------------------------------------------------------
// Scratch (__device__ globals; allocation-free contract)
// ---------------------------------------------------------------------------
__device__ __align__(16) float g_Xt [M_*D_];            // X, tf32-rounded
__device__ __align__(16) float g_Wt [4*(size_t)D_*D_];  // q,k,v,o weights tf32
__device__ __align__(16) float g_AOt[M_*D_];            // attn out (tf32)
__device__ __align__(16) float g_Q[B_*H_*S_*DK_];       // [B,H,S,DK] tf32, *log2(e)/8
__device__ __align__(16) float g_K[B_*H_*S_*DK_];       // [B,H,S,DK] tf32
__device__ __align__(16) float g_V[B_*H_*S_*DK_];       // [B,H,DK,S] tf32 (transposed)

// ---------------------------------------------------------------------------
// PTX wrappers (arch-neutral sm_80-class)
// ---------------------------------------------------------------------------
__device__ __forceinline__ uint32_t smem_u32(const void* p) {
    uint32_t a;
    asm("{ .reg .u64 t; cvta.to.shared.u64 t, %1; cvt.u32.u64 %0, t; }"
        : "=r"(a) : "l"(p));
    return a;
}
__device__ __forceinline__ void cp16(uint32_t dst, const void* src) {
    asm volatile("cp.async.cg.shared.global [%0], [%1], 16;"
                 :: "r"(dst), "l"(src));
}
#define CP_COMMIT() asm volatile("cp.async.commit_group;")
#define CP_WAIT1()  asm volatile("cp.async.wait_group 1;")

__device__ __forceinline__ void mma_tf32(float (&d)[4], const uint32_t (&a)[4],
                                         uint32_t b0, uint32_t b1) {
    asm volatile(
        "mma.sync.aligned.m16n8k8.row.col.f32.tf32.tf32.f32 "
        "{%0,%1,%2,%3}, {%4,%5,%6,%7}, {%8,%9}, {%0,%1,%2,%3};"
        : "+f"(d[0]), "+f"(d[1]), "+f"(d[2]), "+f"(d[3])
        : "r"(a[0]), "r"(a[1]), "r"(a[2]), "r"(a[3]), "r"(b0), "r"(b1));
}
__device__ __forceinline__ float ex2f(float x) {
    float y; asm("ex2.approx.f32 %0, %1;" : "=f"(y) : "f"(x)); return y;
}
__device__ __forceinline__ float tf32r(float x) {
    uint32_t r; asm("cvt.rna.tf32.f32 %0, %1;" : "=r"(r) : "f"(x));
    return __uint_as_float(r);
}

#define SC_Q 0.18033688011112042f   // log2(e)/8, folded into Q at projection

// ---------------------------------------------------------------------------
// Prep kernels: rna-round to tf32 (mma would TRUNCATE raw fp32 — 2x the error)
// ---------------------------------------------------------------------------
__global__ __launch_bounds__(256)
void conv_tf32(const float* __restrict__ src, float* __restrict__ dst, int n)
{
    int i = (blockIdx.x * blockDim.x + threadIdx.x) * 4;
    if (i >= n) return;
    float4 v = *(const float4*)(src + i);
    *(float4*)(dst + i) = make_float4(tf32r(v.x), tf32r(v.y), tf32r(v.z), tf32r(v.w));
}
__global__ __launch_bounds__(256)
void conv_w4(const float* __restrict__ w0, const float* __restrict__ w1,
             const float* __restrict__ w2, const float* __restrict__ w3,
             float* __restrict__ dst)
{
    const float* srcs[4] = {w0, w1, w2, w3};
    const float* src = srcs[blockIdx.y];
    float* d = dst + (size_t)blockIdx.y * D_ * D_;
    int i = (blockIdx.x * blockDim.x + threadIdx.x) * 4;
    float4 v = *(const float4*)(src + i);
    *(float4*)(d + i) = make_float4(tf32r(v.x), tf32r(v.y), tf32r(v.z), tf32r(v.w));
}

// ---------------------------------------------------------------------------
// Single-pass tf32 GEMM: C[m,n] = sum_k A[m,k]*W[n,k], fp32 accum.
// CTA 128x64, BK=32, 8 warps (32x32 tiles), 3-stage cp.async, fp32 smem.
// DEST: 0 = Cout fp32 [M,D]
//       1 = g_Q (+RoPE, *SC_Q) [B,H,S,DK]   2 = g_K (+RoPE) [B,H,S,DK]
//       3 = g_V transposed [B,H,DK,S]
// ---------------------------------------------------------------------------
#define BM 128
#define BN 64
#define BK 32
#define NIT (D_/BK)
#define TROW 36
#define TSB_OFF (BM*TROW)
#define TSTG ((BM*TROW + BN*TROW)*4)    // 27648 bytes
#define TSMEM (3*TSTG)                  // 82944

template<int DEST>
__global__ __launch_bounds__(256)
void gemm_tf32(const float* __restrict__ A, const float* __restrict__ W,
               float* __restrict__ Cout, const int* __restrict__ tokpos)
{
    extern __shared__ __align__(16) char smem[];
    const int tid  = threadIdx.x;
    const int lane = tid & 31, w = tid >> 5;
    const int wm = (w & 3) * 32;
    const int wn = (w >> 2) * 32;
    const int m0 = blockIdx.x * BM;
    const int n0 = blockIdx.y * BN;
    const int rg = lane >> 2, tc = lane & 3;

    auto load_stage = [&](int st, int it) {
        float* s = (float*)(smem + st * TSTG);
        const int kk = it * BK;
#pragma unroll
        for (int i = 0; i < 4; i++) {           // A: 128 rows x 8 chunks
            int idx = tid + i * 256;
            int row = idx >> 3, ch = idx & 7;
            cp16(smem_u32(s + row * TROW + ch * 4),
                 A + (size_t)(m0 + row) * D_ + kk + ch * 4);
        }
        float* sB = s + TSB_OFF;
#pragma unroll
        for (int i = 0; i < 2; i++) {           // B: 64 rows x 8 chunks
            int idx = tid + i * 256;
            int row = idx >> 3, ch = idx & 7;
            cp16(smem_u32(sB + row * TROW + ch * 4),
                 W + (size_t)(n0 + row) * D_ + kk + ch * 4);
        }
    };

    float acc[2][4][4];
#pragma unroll
    for (int mt = 0; mt < 2; mt++)
#pragma unroll
        for (int nt = 0; nt < 4; nt++)
#pragma unroll
            for (int r = 0; r < 4; r++) acc[mt][nt][r] = 0.f;

    load_stage(0, 0); CP_COMMIT();
    load_stage(1, 1); CP_COMMIT();

    for (int it = 0; it < NIT; it++) {
        CP_WAIT1();
        __syncthreads();
        if (it + 2 < NIT) load_stage((it + 2) % 3, it + 2);
        CP_COMMIT();

        const uint32_t* s  = (const uint32_t*)(smem + (it % 3) * TSTG);
        const uint32_t* sB = s + TSB_OFF;
#pragma unroll
        for (int ks = 0; ks < 4; ks++) {
            uint32_t a[2][4];
#pragma unroll
            for (int mt = 0; mt < 2; mt++) {
                const uint32_t* base = s + (wm + mt * 16 + rg) * TROW + ks * 8 + tc;
                a[mt][0] = base[0];
                a[mt][1] = base[8 * TROW];
                a[mt][2] = base[4];
                a[mt][3] = base[8 * TROW + 4];
            }
#pragma unroll
            for (int nt = 0; nt < 4; nt++) {
                const uint32_t* bp = sB + (wn + nt * 8 + rg) * TROW + ks * 8 + tc;
                const uint32_t b0 = bp[0], b1 = bp[4];
#pragma unroll
                for (int mt = 0; mt < 2; mt++)
                    mma_tf32(acc[mt][nt], a[mt], b0, b1);
            }
        }
    }

#pragma unroll
    for (int mt = 0; mt < 2; mt++) {
        const int r0 = m0 + wm + mt * 16 + (lane >> 2);
#pragma unroll
        for (int nt = 0; nt < 4; nt++) {
            const int ncol = n0 + wn + nt * 8 + (lane & 3) * 2;
            if (DEST == 0) {
                *(float2*)(Cout + (size_t)r0 * D_ + ncol) =
                    make_float2(acc[mt][nt][0], acc[mt][nt][1]);
                *(float2*)(Cout + (size_t)(r0 + 8) * D_ + ncol) =
                    make_float2(acc[mt][nt][2], acc[mt][nt][3]);
            } else if (DEST == 3) {
                const int h = ncol >> 6, dk = ncol & 63;
#pragma unroll
                for (int rr = 0; rr < 2; rr++) {
                    const int m = r0 + rr * 8;
                    const int bb = m >> 11, ss = m & (S_ - 1);
                    size_t base = ((size_t)(bb * H_ + h)) * DK_ * S_;
                    g_V[base + (size_t)dk * S_ + ss]       = tf32r(acc[mt][nt][2 * rr]);
                    g_V[base + (size_t)(dk + 1) * S_ + ss] = tf32r(acc[mt][nt][2 * rr + 1]);
                }
            } else {
                float* Dst = (DEST == 1) ? g_Q : g_K;
                const int h = ncol >> 6, dk = ncol & 63;   // dk even: RoPE pair
                const float fr = powf(10000.f, -(float)dk / 64.f);
#pragma unroll
                for (int rr = 0; rr < 2; rr++) {
                    const int m = r0 + rr * 8;
                    const int bb = m >> 11, ss = m & (S_ - 1);
                    const float pos = (float)tokpos[ss];
                    float sn, cs;
                    sincosf(pos * fr, &sn, &cs);
                    float e  = acc[mt][nt][2 * rr];
                    float od = acc[mt][nt][2 * rr + 1];
                    float v0 = e * cs - od * sn;
                    float v1 = e * sn + od * cs;
                    if (DEST == 1) { v0 *= SC_Q; v1 *= SC_Q; }
                    size_t idx = (((size_t)(bb * H_ + h)) * S_ + ss) * DK_ + dk;
                    *(float2*)(Dst + idx) = make_float2(tf32r(v0), tf32r(v1));
                }
            }
        }
    }
}

// ---------------------------------------------------------------------------
// Flash attention, single-pass tf32 (QK^T and PV). CTA = 64q x 64kv, 4 warps.
// Q pre-scaled by log2(e)/8. V pre-transposed [d][s].
// ---------------------------------------------------------------------------
#define AST 68                               // smem row stride in floats
#define OKV0 (64*AST)
#define OP   (64*AST + 2*2*64*AST)
#define ATT_FLOATS (OP + 4*16*AST)
#define ATT_SMEM (ATT_FLOATS*4)              // 104448

__global__ __launch_bounds__(128)
void attn_tf32()
{
    extern __shared__ __align__(16) float sm[];
    uint32_t* smw = (uint32_t*)sm;
    const int tid = threadIdx.x;
    const int lane = tid & 31, w = tid >> 5;
    const int rg = lane >> 2, tc = lane & 3;
    const int qt = (int)(gridDim.x - 1 - blockIdx.x);
    const int h  = blockIdx.y, b = blockIdx.z;
    const int q0 = qt * 64;
    const size_t gqk = ((size_t)(b * H_ + h)) * S_ * DK_;
    const size_t gvt = ((size_t)(b * H_ + h)) * DK_ * S_;

#pragma unroll
    for (int i = 0; i < 8; i++) {
        int idx = tid + i * 128;
        int r = idx >> 4, ch = idx & 15;
        cp16(smem_u32(sm + r * AST + ch * 4),
             g_Q + gqk + (size_t)(q0 + r) * DK_ + ch * 4);
    }
    auto load_kv = [&](int st, int kt) {
        float* sK = sm + OKV0 + st * (2 * 64 * AST);
        float* sV = sK + 64 * AST;
#pragma unroll
        for (int i = 0; i < 8; i++) {
            int idx = tid + i * 128;
            int r = idx >> 4, ch = idx & 15;
            cp16(smem_u32(sK + r * AST + ch * 4),
                 g_K + gqk + (size_t)(kt * 64 + r) * DK_ + ch * 4);
            cp16(smem_u32(sV + r * AST + ch * 4),
                 g_V + gvt + (size_t)r * S_ + kt * 64 + ch * 4);
        }
    };
    load_kv(0, 0); CP_COMMIT();
    if (qt >= 1) load_kv(1, 1);
    CP_COMMIT();

    CP_WAIT1();
    __syncthreads();

    uint32_t qf[8][4];
    {
        const uint32_t* q = smw + (w * 16 + rg) * AST;
#pragma unroll
        for (int ks = 0; ks < 8; ks++) {
            qf[ks][0] = q[ks * 8 + tc];
            qf[ks][1] = q[8 * AST + ks * 8 + tc];
            qf[ks][2] = q[ks * 8 + tc + 4];
            qf[ks][3] = q[8 * AST + ks * 8 + tc + 4];
        }
    }

    float o[8][4];
#pragma unroll
    for (int d = 0; d < 8; d++)
#pragma unroll
        for (int r = 0; r < 4; r++) o[d][r] = 0.f;
    float mi0 = -1e30f, mi1 = -1e30f, li0 = 0.f, li1 = 0.f;
    const int row_lo = w * 16 + rg;
    const int colx   = 2 * tc;
    float*    pwf = sm  + OP + w * 16 * AST;
    uint32_t* pww = smw + OP + w * 16 * AST;

    for (int kt = 0; kt <= qt; kt++) {
        if (kt) { CP_WAIT1(); __syncthreads(); }
        const uint32_t* sK = smw + OKV0 + (kt & 1) * (2 * 64 * AST);
        const uint32_t* sV = sK + 64 * AST;

        float s[8][4];
#pragma unroll
        for (int nt = 0; nt < 8; nt++)
#pragma unroll
            for (int r = 0; r < 4; r++) s[nt][r] = 0.f;
#pragma unroll
        for (int ks = 0; ks < 8; ks++)
#pragma unroll
            for (int nt = 0; nt < 8; nt++) {
                const uint32_t* kp = sK + (nt * 8 + rg) * AST + ks * 8 + tc;
                mma_tf32(s[nt], qf[ks], kp[0], kp[4]);
            }

        if (kt == qt) {
#pragma unroll
            for (int nt = 0; nt < 8; nt++) {
                const int c = nt * 8 + colx;
                if (c     > row_lo)     s[nt][0] = -1e30f;
                if (c + 1 > row_lo)     s[nt][1] = -1e30f;
                if (c     > row_lo + 8) s[nt][2] = -1e30f;
                if (c + 1 > row_lo + 8) s[nt][3] = -1e30f;
            }
        }

        float r0 = -1e30f, r1 = -1e30f;
#pragma unroll
        for (int nt = 0; nt < 8; nt++) {
            r0 = fmaxf(r0, fmaxf(s[nt][0], s[nt][1]));
            r1 = fmaxf(r1, fmaxf(s[nt][2], s[nt][3]));
        }
        r0 = fmaxf(r0, __shfl_xor_sync(0xffffffffu, r0, 1));
        r0 = fmaxf(r0, __shfl_xor_sync(0xffffffffu, r0, 2));
        r1 = fmaxf(r1, __shfl_xor_sync(0xffffffffu, r1, 1));
        r1 = fmaxf(r1, __shfl_xor_sync(0xffffffffu, r1, 2));
        const float mn0 = fmaxf(mi0, r0), mn1 = fmaxf(mi1, r1);
        const float c0 = ex2f(mi0 - mn0), c1 = ex2f(mi1 - mn1);
        float sum0 = 0.f, sum1 = 0.f;
#pragma unroll
        for (int nt = 0; nt < 8; nt++) {
            s[nt][0] = ex2f(s[nt][0] - mn0);
            s[nt][1] = ex2f(s[nt][1] - mn0);
            s[nt][2] = ex2f(s[nt][2] - mn1);
            s[nt][3] = ex2f(s[nt][3] - mn1);
            sum0 += s[nt][0] + s[nt][1];
            sum1 += s[nt][2] + s[nt][3];
        }
        sum0 += __shfl_xor_sync(0xffffffffu, sum0, 1);
        sum0 += __shfl_xor_sync(0xffffffffu, sum0, 2);
        sum1 += __shfl_xor_sync(0xffffffffu, sum1, 1);
        sum1 += __shfl_xor_sync(0xffffffffu, sum1, 2);
        li0 = li0 * c0 + sum0; li1 = li1 * c1 + sum1;
        mi0 = mn0; mi1 = mn1;
#pragma unroll
        for (int d = 0; d < 8; d++) {
            o[d][0] *= c0; o[d][1] *= c0; o[d][2] *= c1; o[d][3] *= c1;
        }

#pragma unroll
        for (int nt = 0; nt < 8; nt++) {
            *(float2*)(pwf + rg * AST + nt * 8 + colx) =
                make_float2(tf32r(s[nt][0]), tf32r(s[nt][1]));
            *(float2*)(pwf + (rg + 8) * AST + nt * 8 + colx) =
                make_float2(tf32r(s[nt][2]), tf32r(s[nt][3]));
        }
        __syncwarp();

#pragma unroll
        for (int ks = 0; ks < 8; ks++) {
            uint32_t a[4];
            const uint32_t* pb = pww + rg * AST + ks * 8 + tc;
            a[0] = pb[0];
            a[1] = pb[8 * AST];
            a[2] = pb[4];
            a[3] = pb[8 * AST + 4];
#pragma unroll
            for (int nt = 0; nt < 8; nt++) {
                const uint32_t* vp = sV + (nt * 8 + rg) * AST + ks * 8 + tc;
                mma_tf32(o[nt], a, vp[0], vp[4]);
            }
        }

        __syncthreads();
        if (kt + 2 <= qt) load_kv(kt & 1, kt + 2);
        CP_COMMIT();
    }

    const float inv0 = 1.f / li0, inv1 = 1.f / li1;
    const int grow0 = q0 + row_lo;
#pragma unroll
    for (int d = 0; d < 8; d++) {
        const int col = h * 64 + d * 8 + colx;
        size_t i0 = ((size_t)b * S_ + grow0) * D_ + col;
        size_t i1 = ((size_t)b * S_ + grow0 + 8) * D_ + col;
        *(float2*)(g_AOt + i0) =
            make_float2(tf32r(o[d][0] * inv0), tf32r(o[d][1] * inv0));
        *(float2*)(g_AOt + i1) =
            make_float2(tf32r(o[d][2] * inv1), tf32r(o[d][3] * inv1));
    }
}

// ---------------------------------------------------------------------------
// Host
// ---------------------------------------------------------------------------
extern "C" void kernel_launch(void* const* d_in, const int* in_sizes, int n_in,
                              void* d_out, int out_size)
{
    const float* x  = (const float*)d_in[0];
    const float* qw = (const float*)d_in[1];
    const float* kw = (const float*)d_in[2];
    const float* vw = (const float*)d_in[3];
    const float* ow = (const float*)d_in[4];
    const int*   tp = (const int*)d_in[6];
    float* out = (float*)d_out;

    void *xt, *wt, *aot;
    cudaGetSymbolAddress(&xt,  g_Xt);
    cudaGetSymbolAddress(&wt,  g_Wt);
    cudaGetSymbolAddress(&aot, g_AOt);
    float* Xt  = (float*)xt;
    float* Wt  = (float*)wt;
    float* AOt = (float*)aot;

    conv_tf32<<<M_*D_/4/256, 256>>>(x, Xt, M_*D_);
    dim3 wgrid(D_*D_/4/256, 4);
    conv_w4<<<wgrid, 256>>>(qw, kw, vw, ow, Wt);

    cudaFuncSetAttribute(gemm_tf32<0>, cudaFuncAttributeMaxDynamicSharedMemorySize, TSMEM);
    cudaFuncSetAttribute(gemm_tf32<1>, cudaFuncAttributeMaxDynamicSharedMemorySize, TSMEM);
    cudaFuncSetAttribute(gemm_tf32<2>, cudaFuncAttributeMaxDynamicSharedMemorySize, TSMEM);
    cudaFuncSetAttribute(gemm_tf32<3>, cudaFuncAttributeMaxDynamicSharedMemorySize, TSMEM);
    cudaFuncSetAttribute(attn_tf32, cudaFuncAttributeMaxDynamicSharedMemorySize, ATT_SMEM);

    dim3 ggrid(M_ / BM, D_ / BN);   // (32, 16)
    gemm_tf32<1><<<ggrid, 256, TSMEM>>>(Xt, Wt,                       nullptr, tp);
    gemm_tf32<2><<<ggrid, 256, TSMEM>>>(Xt, Wt + 1*(size_t)D_*D_,     nullptr, tp);
    gemm_tf32<3><<<ggrid, 256, TSMEM>>>(Xt, Wt + 2*(size_t)D_*D_,     nullptr, tp);

    dim3 agrid(S_ / 64, H_, B_);    // (32, 16, 2)
    attn_tf32<<<agrid, 128, ATT_SMEM>>>();

    gemm_tf32<0><<<ggrid, 256, TSMEM>>>(AOt, Wt + 3*(size_t)D_*D_, out, tp);
}

// round 8
// speedup vs baseline: 3.3471x; 1.0753x over previous
#include <cuda_runtime.h>
#include <math.h>
#include <stdint.h>

#define B_  2
#define S_  2048
#define D_  1024
#define H_  16
#define DK_ 64
#define M_  (B_*S_)

// k-group permutation: within each 8-wide k group, position 2i holds logical
// col i, position 2i+1 holds logical col i+4  ([0,4,1,5,2,6,3,7]).
// Applied identically to BOTH mma operands -> results bit-exact, fragment
// loads become LDS.64 pairs (tc, tc+4).
#define PERM8(j) (((j) < 4) ? 2*(j) : 2*(j) - 7)

// ---------------------------------------------------------------------------
// Scratch (__device__ globals; allocation-free contract)
// ---------------------------------------------------------------------------
__device__ __align__(16) float g_Xt [M_*D_];            // X tf32, k-permuted
__device__ __align__(16) float g_Wt [4*(size_t)D_*D_];  // weights tf32, k-permuted
__device__ __align__(16) float g_AOt[M_*D_];            // attn out tf32, k-permuted
__device__ __align__(16) float g_Q[B_*H_*S_*DK_];       // [B,H,S,DK] dk-permuted, *log2(e)/8
__device__ __align__(16) float g_K[B_*H_*S_*DK_];       // [B,H,S,DK] dk-permuted
__device__ __align__(16) float g_V[B_*H_*S_*DK_];       // [B,H,DK,S] s-permuted

// ---------------------------------------------------------------------------
// PTX wrappers
// ---------------------------------------------------------------------------
__device__ __forceinline__ uint32_t smem_u32(const void* p) {
    uint32_t a;
    asm("{ .reg .u64 t; cvta.to.shared.u64 t, %1; cvt.u32.u64 %0, t; }"
        : "=r"(a) : "l"(p));
    return a;
}
__device__ __forceinline__ void cp16(uint32_t dst, const void* src) {
    asm volatile("cp.async.cg.shared.global [%0], [%1], 16;"
                 :: "r"(dst), "l"(src));
}
#define CP_COMMIT() asm volatile("cp.async.commit_group;")
#define CP_WAIT1()  asm volatile("cp.async.wait_group 1;")

__device__ __forceinline__ void mma_tf32(float (&d)[4], const uint32_t (&a)[4],
                                         uint32_t b0, uint32_t b1) {
    asm volatile(
        "mma.sync.aligned.m16n8k8.row.col.f32.tf32.tf32.f32 "
        "{%0,%1,%2,%3}, {%4,%5,%6,%7}, {%8,%9}, {%0,%1,%2,%3};"
        : "+f"(d[0]), "+f"(d[1]), "+f"(d[2]), "+f"(d[3])
        : "r"(a[0]), "r"(a[1]), "r"(a[2]), "r"(a[3]), "r"(b0), "r"(b1));
}
__device__ __forceinline__ float ex2f(float x) {
    float y; asm("ex2.approx.f32 %0, %1;" : "=f"(y) : "f"(x)); return y;
}
__device__ __forceinline__ float tf32r(float x) {
    uint32_t r; asm("cvt.rna.tf32.f32 %0, %1;" : "=r"(r) : "f"(x));
    return __uint_as_float(r);
}

#define SC_Q 0.18033688011112042f   // log2(e)/8, folded into Q

// ---------------------------------------------------------------------------
// Prep: tf32-round (rna; mma truncates raw fp32) + k-group permute.
// Each thread handles 8 consecutive cols (one permutation group).
// ---------------------------------------------------------------------------
__device__ __forceinline__ void conv8(const float* src, float* dst, size_t i) {
    float4 v = *(const float4*)(src + i);
    float4 w = *(const float4*)(src + i + 4);
    *(float2*)(dst + i)     = make_float2(tf32r(v.x), tf32r(w.x));
    *(float2*)(dst + i + 2) = make_float2(tf32r(v.y), tf32r(w.y));
    *(float2*)(dst + i + 4) = make_float2(tf32r(v.z), tf32r(w.z));
    *(float2*)(dst + i + 6) = make_float2(tf32r(v.w), tf32r(w.w));
}
__global__ __launch_bounds__(256)
void conv_x(const float* __restrict__ src, float* __restrict__ dst)
{
    size_t i = ((size_t)blockIdx.x * blockDim.x + threadIdx.x) * 8;
    conv8(src, dst, i);
}
__global__ __launch_bounds__(256)
void conv_w4(const float* __restrict__ w0, const float* __restrict__ w1,
             const float* __restrict__ w2, const float* __restrict__ w3,
             float* __restrict__ dst)
{
    const float* srcs[4] = {w0, w1, w2, w3};
    const float* src = srcs[blockIdx.y];
    float* d = dst + (size_t)blockIdx.y * D_ * D_;
    size_t i = ((size_t)blockIdx.x * blockDim.x + threadIdx.x) * 8;
    conv8(src, d, i);
}

// ---------------------------------------------------------------------------
// Single-pass tf32 GEMM, permuted operands, 2-stage cp.async, 3 CTA/SM.
// CTA 128x64, BK=32, 8 warps (32x32 tiles).
// DEST: 0 = Cout fp32 [M,D] (NOT permuted — final output)
//       1 = g_Q (+RoPE,*SC_Q)  2 = g_K (+RoPE)  [B,H,S,DK] dk-permuted
//       3 = g_V transposed [B,H,DK,S] s-permuted
// ---------------------------------------------------------------------------
#define BM 128
#define BN 64
#define BK 32
#define NIT (D_/BK)
#define TROW 40
#define TSB_OFF (BM*TROW)
#define TSTG ((BM*TROW + BN*TROW)*4)    // 30720 bytes
#define TSMEM (2*TSTG)                  // 61440 -> 3 CTA/SM

template<int DEST>
__global__ __launch_bounds__(256, 3)
void gemm_tf32(const float* __restrict__ A, const float* __restrict__ W,
               float* __restrict__ Cout, const int* __restrict__ tokpos)
{
    extern __shared__ __align__(16) char smem[];
    const int tid  = threadIdx.x;
    const int lane = tid & 31, w = tid >> 5;
    const int wm = (w & 3) * 32;
    const int wn = (w >> 2) * 32;
    const int m0 = blockIdx.x * BM;
    const int n0 = blockIdx.y * BN;
    const int rg = lane >> 2, tc = lane & 3;

    auto load_stage = [&](int st, int it) {
        float* s = (float*)(smem + st * TSTG);
        const int kk = it * BK;
#pragma unroll
        for (int i = 0; i < 4; i++) {           // A: 128 rows x 8 chunks
            int idx = tid + i * 256;
            int row = idx >> 3, ch = idx & 7;
            cp16(smem_u32(s + row * TROW + ch * 4),
                 A + (size_t)(m0 + row) * D_ + kk + ch * 4);
        }
        float* sB = s + TSB_OFF;
#pragma unroll
        for (int i = 0; i < 2; i++) {           // B: 64 rows x 8 chunks
            int idx = tid + i * 256;
            int row = idx >> 3, ch = idx & 7;
            cp16(smem_u32(sB + row * TROW + ch * 4),
                 W + (size_t)(n0 + row) * D_ + kk + ch * 4);
        }
    };

    float acc[2][4][4];
#pragma unroll
    for (int mt = 0; mt < 2; mt++)
#pragma unroll
        for (int nt = 0; nt < 4; nt++)
#pragma unroll
            for (int r = 0; r < 4; r++) acc[mt][nt][r] = 0.f;

    load_stage(0, 0); CP_COMMIT();
    load_stage(1, 1); CP_COMMIT();

    for (int it = 0; it < NIT; it++) {
        CP_WAIT1();
        __syncthreads();

        const float* s  = (const float*)(smem + (it & 1) * TSTG);
        const float* sB = s + TSB_OFF;
#pragma unroll
        for (int ks = 0; ks < 4; ks++) {
            uint32_t a[2][4];
#pragma unroll
            for (int mt = 0; mt < 2; mt++) {
                const float* base = s + (wm + mt * 16 + rg) * TROW + ks * 8 + 2 * tc;
                uint2 r1 = *(const uint2*)(base);             // (a0, a2)
                uint2 r2 = *(const uint2*)(base + 8 * TROW);  // (a1, a3)
                a[mt][0] = r1.x; a[mt][1] = r2.x; a[mt][2] = r1.y; a[mt][3] = r2.y;
            }
#pragma unroll
            for (int nt = 0; nt < 4; nt++) {
                uint2 bb = *(const uint2*)(sB + (wn + nt * 8 + rg) * TROW + ks * 8 + 2 * tc);
#pragma unroll
                for (int mt = 0; mt < 2; mt++)
                    mma_tf32(acc[mt][nt], a[mt], bb.x, bb.y);
            }
        }
        __syncthreads();
        if (it + 2 < NIT) load_stage(it & 1, it + 2);
        CP_COMMIT();
    }

#pragma unroll
    for (int mt = 0; mt < 2; mt++) {
        const int r0 = m0 + wm + mt * 16 + (lane >> 2);
#pragma unroll
        for (int nt = 0; nt < 4; nt++) {
            const int ncol = n0 + wn + nt * 8 + (lane & 3) * 2;   // even
            if (DEST == 0) {
                *(float2*)(Cout + (size_t)r0 * D_ + ncol) =
                    make_float2(acc[mt][nt][0], acc[mt][nt][1]);
                *(float2*)(Cout + (size_t)(r0 + 8) * D_ + ncol) =
                    make_float2(acc[mt][nt][2], acc[mt][nt][3]);
            } else if (DEST == 3) {
                const int h = ncol >> 6, dk = ncol & 63;
#pragma unroll
                for (int rr = 0; rr < 2; rr++) {
                    const int m = r0 + rr * 8;
                    const int bb = m >> 11, ss = m & (S_ - 1);
                    const int sp = (ss & ~7) + PERM8(ss & 7);   // s-permuted
                    size_t base = ((size_t)(bb * H_ + h)) * DK_ * S_;
                    g_V[base + (size_t)dk * S_ + sp]       = tf32r(acc[mt][nt][2 * rr]);
                    g_V[base + (size_t)(dk + 1) * S_ + sp] = tf32r(acc[mt][nt][2 * rr + 1]);
                }
            } else {
                float* Dst = (DEST == 1) ? g_Q : g_K;
                const int h = ncol >> 6, dk = ncol & 63;   // even: RoPE pair
                const int dg = dk & ~7, dl = dk & 7;
                const int p0 = dg + PERM8(dl);
                const int p1 = dg + PERM8(dl + 1);
                const float fr = powf(10000.f, -(float)dk / 64.f);
#pragma unroll
                for (int rr = 0; rr < 2; rr++) {
                    const int m = r0 + rr * 8;
                    const int bb = m >> 11, ss = m & (S_ - 1);
                    const float pos = (float)tokpos[ss];
                    float sn, cs;
                    sincosf(pos * fr, &sn, &cs);
                    float e  = acc[mt][nt][2 * rr];
                    float od = acc[mt][nt][2 * rr + 1];
                    float v0 = e * cs - od * sn;
                    float v1 = e * sn + od * cs;
                    if (DEST == 1) { v0 *= SC_Q; v1 *= SC_Q; }
                    size_t ib = (((size_t)(bb * H_ + h)) * S_ + ss) * DK_;
                    Dst[ib + p0] = tf32r(v0);
                    Dst[ib + p1] = tf32r(v1);
                }
            }
        }
    }
}

// ---------------------------------------------------------------------------
// Flash attention, single-pass tf32, permuted LDS.64 fragments.
// CTA = 64q x 64kv, 4 warps. Q pre-scaled; V pre-transposed+s-permuted.
// ---------------------------------------------------------------------------
#define AST 72                               // smem row stride (floats)
#define OKV0 (64*AST)
#define OP   (64*AST + 2*2*64*AST)           // = 23040
#define ATT_FLOATS (OP + 64*AST)             // 27648
#define ATT_SMEM (ATT_FLOATS*4)              // 110592 -> 2 CTA/SM

__global__ __launch_bounds__(128)
void attn_tf32()
{
    extern __shared__ __align__(16) float sm[];
    const int tid = threadIdx.x;
    const int lane = tid & 31, w = tid >> 5;
    const int rg = lane >> 2, tc = lane & 3;
    const int qt = (int)(gridDim.x - 1 - blockIdx.x);
    const int h  = blockIdx.y, b = blockIdx.z;
    const int q0 = qt * 64;
    const size_t gqk = ((size_t)(b * H_ + h)) * S_ * DK_;
    const size_t gvt = ((size_t)(b * H_ + h)) * DK_ * S_;

#pragma unroll
    for (int i = 0; i < 8; i++) {
        int idx = tid + i * 128;
        int r = idx >> 4, ch = idx & 15;
        cp16(smem_u32(sm + r * AST + ch * 4),
             g_Q + gqk + (size_t)(q0 + r) * DK_ + ch * 4);
    }
    auto load_kv = [&](int st, int kt) {
        float* sK = sm + OKV0 + st * (2 * 64 * AST);
        float* sV = sK + 64 * AST;
#pragma unroll
        for (int i = 0; i < 8; i++) {
            int idx = tid + i * 128;
            int r = idx >> 4, ch = idx & 15;
            cp16(smem_u32(sK + r * AST + ch * 4),
                 g_K + gqk + (size_t)(kt * 64 + r) * DK_ + ch * 4);
            cp16(smem_u32(sV + r * AST + ch * 4),
                 g_V + gvt + (size_t)r * S_ + kt * 64 + ch * 4);
        }
    };
    load_kv(0, 0); CP_COMMIT();
    if (qt >= 1) load_kv(1, 1);
    CP_COMMIT();

    CP_WAIT1();
    __syncthreads();

    // preload Q fragments (fixed across kv tiles); permuted pairs
    uint32_t qf[8][4];
    {
        const float* q = sm + (w * 16 + rg) * AST + 2 * tc;
#pragma unroll
        for (int ks = 0; ks < 8; ks++) {
            uint2 r1 = *(const uint2*)(q + ks * 8);             // (a0, a2)
            uint2 r2 = *(const uint2*)(q + 8 * AST + ks * 8);   // (a1, a3)
            qf[ks][0] = r1.x; qf[ks][1] = r2.x; qf[ks][2] = r1.y; qf[ks][3] = r2.y;
        }
    }

    float o[8][4];
#pragma unroll
    for (int d = 0; d < 8; d++)
#pragma unroll
        for (int r = 0; r < 4; r++) o[d][r] = 0.f;
    float mi0 = -1e30f, mi1 = -1e30f, li0 = 0.f, li1 = 0.f;
    const int row_lo = w * 16 + rg;
    const int colx   = 2 * tc;
    // P write positions (s-permuted): cols (2tc, 2tc+1) within 8-group
    const int pp0 = PERM8(colx);
    const int pp1 = PERM8(colx + 1);
    float* pwf = sm + OP + w * 16 * AST;

    for (int kt = 0; kt <= qt; kt++) {
        if (kt) { CP_WAIT1(); __syncthreads(); }
        const float* sK = sm + OKV0 + (kt & 1) * (2 * 64 * AST);
        const float* sV = sK + 64 * AST;

        // ---- S = Q K^T ----
        float s[8][4];
#pragma unroll
        for (int nt = 0; nt < 8; nt++)
#pragma unroll
            for (int r = 0; r < 4; r++) s[nt][r] = 0.f;
#pragma unroll
        for (int ks = 0; ks < 8; ks++)
#pragma unroll
            for (int nt = 0; nt < 8; nt++) {
                uint2 kb = *(const uint2*)(sK + (nt * 8 + rg) * AST + ks * 8 + 2 * tc);
                mma_tf32(s[nt], qf[ks], kb.x, kb.y);
            }

        if (kt == qt) {   // causal mask on diagonal tile
#pragma unroll
            for (int nt = 0; nt < 8; nt++) {
                const int c = nt * 8 + colx;
                if (c     > row_lo)     s[nt][0] = -1e30f;
                if (c + 1 > row_lo)     s[nt][1] = -1e30f;
                if (c     > row_lo + 8) s[nt][2] = -1e30f;
                if (c + 1 > row_lo + 8) s[nt][3] = -1e30f;
            }
        }

        // ---- online softmax (base-2; scale folded into Q) ----
        float r0 = -1e30f, r1 = -1e30f;
#pragma unroll
        for (int nt = 0; nt < 8; nt++) {
            r0 = fmaxf(r0, fmaxf(s[nt][0], s[nt][1]));
            r1 = fmaxf(r1, fmaxf(s[nt][2], s[nt][3]));
        }
        r0 = fmaxf(r0, __shfl_xor_sync(0xffffffffu, r0, 1));
        r0 = fmaxf(r0, __shfl_xor_sync(0xffffffffu, r0, 2));
        r1 = fmaxf(r1, __shfl_xor_sync(0xffffffffu, r1, 1));
        r1 = fmaxf(r1, __shfl_xor_sync(0xffffffffu, r1, 2));
        const float mn0 = fmaxf(mi0, r0), mn1 = fmaxf(mi1, r1);
        const float c0 = ex2f(mi0 - mn0), c1 = ex2f(mi1 - mn1);
        float sum0 = 0.f, sum1 = 0.f;
#pragma unroll
        for (int nt = 0; nt < 8; nt++) {
            s[nt][0] = ex2f(s[nt][0] - mn0);
            s[nt][1] = ex2f(s[nt][1] - mn0);
            s[nt][2] = ex2f(s[nt][2] - mn1);
            s[nt][3] = ex2f(s[nt][3] - mn1);
            sum0 += s[nt][0] + s[nt][1];
            sum1 += s[nt][2] + s[nt][3];
        }
        sum0 += __shfl_xor_sync(0xffffffffu, sum0, 1);
        sum0 += __shfl_xor_sync(0xffffffffu, sum0, 2);
        sum1 += __shfl_xor_sync(0xffffffffu, sum1, 1);
        sum1 += __shfl_xor_sync(0xffffffffu, sum1, 2);
        li0 = li0 * c0 + sum0; li1 = li1 * c1 + sum1;
        mi0 = mn0; mi1 = mn1;
#pragma unroll
        for (int d = 0; d < 8; d++) {
            o[d][0] *= c0; o[d][1] *= c0; o[d][2] *= c1; o[d][3] *= c1;
        }

        // ---- stage P (tf32, s-permuted) in per-warp smem ----
#pragma unroll
        for (int nt = 0; nt < 8; nt++) {
            float* pr0 = pwf + rg * AST + nt * 8;
            float* pr1 = pwf + (rg + 8) * AST + nt * 8;
            pr0[pp0] = tf32r(s[nt][0]); pr0[pp1] = tf32r(s[nt][1]);
            pr1[pp0] = tf32r(s[nt][2]); pr1[pp1] = tf32r(s[nt][3]);
        }
        __syncwarp();

        // ---- O += P V ----
#pragma unroll
        for (int ks = 0; ks < 8; ks++) {
            uint32_t a[4];
            const float* pb = pwf + rg * AST + ks * 8 + 2 * tc;
            uint2 r1v = *(const uint2*)(pb);
            uint2 r2v = *(const uint2*)(pb + 8 * AST);
            a[0] = r1v.x; a[1] = r2v.x; a[2] = r1v.y; a[3] = r2v.y;
#pragma unroll
            for (int nt = 0; nt < 8; nt++) {
                uint2 vb = *(const uint2*)(sV + (nt * 8 + rg) * AST + ks * 8 + 2 * tc);
                mma_tf32(o[nt], a, vb.x, vb.y);
            }
        }

        __syncthreads();
        if (kt + 2 <= qt) load_kv(kt & 1, kt + 2);
        CP_COMMIT();
    }

    // ---- epilogue: normalize, write tf32 k-permuted [B,S,H*DK] ----
    const float inv0 = 1.f / li0, inv1 = 1.f / li1;
    const int grow0 = q0 + row_lo;
    const int op0 = PERM8(colx);        // within d*8 group
    const int op1 = PERM8(colx + 1);
#pragma unroll
    for (int d = 0; d < 8; d++) {
        const int cb = h * 64 + d * 8;
        float* a0 = g_AOt + ((size_t)b * S_ + grow0) * D_ + cb;
        float* a1 = g_AOt + ((size_t)b * S_ + grow0 + 8) * D_ + cb;
        a0[op0] = tf32r(o[d][0] * inv0); a0[op1] = tf32r(o[d][1] * inv0);
        a1[op0] = tf32r(o[d][2] * inv1); a1[op1] = tf32r(o[d][3] * inv1);
    }
}

// ---------------------------------------------------------------------------
// Host
// ---------------------------------------------------------------------------
extern "C" void kernel_launch(void* const* d_in, const int* in_sizes, int n_in,
                              void* d_out, int out_size)
{
    const float* x  = (const float*)d_in[0];
    const float* qw = (const float*)d_in[1];
    const float* kw = (const float*)d_in[2];
    const float* vw = (const float*)d_in[3];
    const float* ow = (const float*)d_in[4];
    const int*   tp = (const int*)d_in[6];
    float* out = (float*)d_out;

    void *xt, *wt, *aot;
    cudaGetSymbolAddress(&xt,  g_Xt);
    cudaGetSymbolAddress(&wt,  g_Wt);
    cudaGetSymbolAddress(&aot, g_AOt);
    float* Xt  = (float*)xt;
    float* Wt  = (float*)wt;
    float* AOt = (float*)aot;

    conv_x<<<M_*D_/8/256, 256>>>(x, Xt);
    dim3 wgrid(D_*D_/8/256, 4);
    conv_w4<<<wgrid, 256>>>(qw, kw, vw, ow, Wt);

    cudaFuncSetAttribute(gemm_tf32<0>, cudaFuncAttributeMaxDynamicSharedMemorySize, TSMEM);
    cudaFuncSetAttribute(gemm_tf32<1>, cudaFuncAttributeMaxDynamicSharedMemorySize, TSMEM);
    cudaFuncSetAttribute(gemm_tf32<2>, cudaFuncAttributeMaxDynamicSharedMemorySize, TSMEM);
    cudaFuncSetAttribute(gemm_tf32<3>, cudaFuncAttributeMaxDynamicSharedMemorySize, TSMEM);
    cudaFuncSetAttribute(attn_tf32, cudaFuncAttributeMaxDynamicSharedMemorySize, ATT_SMEM);

    dim3 ggrid(M_ / BM, D_ / BN);   // (32, 16)
    gemm_tf32<1><<<ggrid, 256, TSMEM>>>(Xt, Wt,                   nullptr, tp);
    gemm_tf32<2><<<ggrid, 256, TSMEM>>>(Xt, Wt + 1*(size_t)D_*D_, nullptr, tp);
    gemm_tf32<3><<<ggrid, 256, TSMEM>>>(Xt, Wt + 2*(size_t)D_*D_, nullptr, tp);

    dim3 agrid(S_ / 64, H_, B_);    // (32, 16, 2)
    attn_tf32<<<agrid, 128, ATT_SMEM>>>();

    gemm_tf32<0><<<ggrid, 256, TSMEM>>>(AOt, Wt + 3*(size_t)D_*D_, out, tp);
}